// round 12
// baseline (speedup 1.0000x reference)
#include <cuda_runtime.h>
#include <cuda_bf16.h>
#include <stdint.h>
#include <math.h>

#define E_DIM 1024
#define H_HEADS 16
#define D_HEAD 64
#define L_MAX 4096

// ---------------------------------------------------------------------------
// Device scratch (allocation-free kernel_launch)
// ---------------------------------------------------------------------------
__device__ __nv_bfloat16 g_xq_h[L_MAX * E_DIM], g_xq_l[L_MAX * E_DIM];
__device__ __nv_bfloat16 g_xk_h[L_MAX * E_DIM], g_xk_l[L_MAX * E_DIM];
__device__ __nv_bfloat16 g_xv_h[L_MAX * E_DIM], g_xv_l[L_MAX * E_DIM];
__device__ __nv_bfloat16 g_wq_h[E_DIM * E_DIM], g_wq_l[E_DIM * E_DIM];
__device__ __nv_bfloat16 g_wk_h[E_DIM * E_DIM], g_wk_l[E_DIM * E_DIM];
__device__ __nv_bfloat16 g_wv_h[E_DIM * E_DIM], g_wv_l[E_DIM * E_DIM];
__device__ __nv_bfloat16 g_fc_h[E_DIM * E_DIM], g_fc_l[E_DIM * E_DIM];
__device__ __nv_bfloat16 g_q_h[L_MAX * E_DIM], g_q_l[L_MAX * E_DIM];
__device__ __nv_bfloat16 g_k_h[L_MAX * E_DIM], g_k_l[L_MAX * E_DIM];
__device__ __nv_bfloat16 g_vt_h[E_DIM * L_MAX], g_vt_l[E_DIM * L_MAX];   // [E][S]
__device__ __nv_bfloat16 g_o_h[L_MAX * E_DIM], g_o_l[L_MAX * E_DIM];
__device__ float g_attn_fb[(size_t)H_HEADS * L_MAX * L_MAX];

#define DINLINE __device__ __forceinline__

DINLINE uint32_t smem_u32(const void* p) {
    uint32_t a;
    asm("{ .reg .u64 t; cvta.to.shared.u64 t, %1; cvt.u32.u64 %0, t; }" : "=r"(a) : "l"(p));
    return a;
}
DINLINE uint32_t sw128(uint32_t off) { return off ^ ((off >> 3) & 0x70); }

DINLINE void ldsm_x4(uint32_t& r0, uint32_t& r1, uint32_t& r2, uint32_t& r3, uint32_t addr) {
    asm volatile("ldmatrix.sync.aligned.m8n8.x4.shared.b16 {%0,%1,%2,%3}, [%4];"
                 : "=r"(r0), "=r"(r1), "=r"(r2), "=r"(r3) : "r"(addr));
}
DINLINE void ldsm_x2(uint32_t& r0, uint32_t& r1, uint32_t addr) {
    asm volatile("ldmatrix.sync.aligned.m8n8.x2.shared.b16 {%0,%1}, [%2];"
                 : "=r"(r0), "=r"(r1) : "r"(addr));
}
DINLINE void mma16816(float c[4], uint32_t a0, uint32_t a1, uint32_t a2, uint32_t a3,
                      uint32_t b0, uint32_t b1) {
    asm volatile(
        "mma.sync.aligned.m16n8k16.row.col.f32.bf16.bf16.f32 "
        "{%0,%1,%2,%3}, {%4,%5,%6,%7}, {%8,%9}, {%0,%1,%2,%3};"
        : "+f"(c[0]), "+f"(c[1]), "+f"(c[2]), "+f"(c[3])
        : "r"(a0), "r"(a1), "r"(a2), "r"(a3), "r"(b0), "r"(b1));
}
DINLINE void cp16(uint32_t dst, const void* src) {
    asm volatile("cp.async.ca.shared.global [%0], [%1], 16;" :: "r"(dst), "l"(src));
}

DINLINE uint32_t bf2u(__nv_bfloat16 a, __nv_bfloat16 b) {
    __nv_bfloat162 t = __halves2bfloat162(a, b);
    return *reinterpret_cast<uint32_t*>(&t);
}
DINLINE uint32_t packf_hi(float a, float b) {
    return bf2u(__float2bfloat16(a), __float2bfloat16(b));
}

// ---------------------------------------------------------------------------
// Core: one KC=64 chunk, bf16x3 emulated fp32 (hi*hi + hi*lo + lo*hi).
// ---------------------------------------------------------------------------
template<int MT, int NT>
DINLINE void compute_chunk(uint32_t aHi, uint32_t aLo, uint32_t bHi, uint32_t bLo,
                           int warpM, int warpN, int lane, float (&acc)[MT][NT][4])
{
    const int arow = lane & 15, asel = lane >> 4;
    const int brow = lane & 7,  bsel = (lane >> 3) & 1;
#pragma unroll
    for (int ks = 0; ks < 4; ks++) {
        uint32_t bh[NT][2], bl[NT][2];
        uint32_t ah[MT][4], al[MT][4];
        const uint32_t bcol = (uint32_t)(ks * 16 + bsel * 8) * 2;
#pragma unroll
        for (int nt = 0; nt < NT; nt++) {
            uint32_t off = sw128((uint32_t)(warpN + nt * 8 + brow) * 128 + bcol);
            ldsm_x2(bh[nt][0], bh[nt][1], bHi + off);
            ldsm_x2(bl[nt][0], bl[nt][1], bLo + off);
        }
        const uint32_t acol = (uint32_t)(ks * 16 + asel * 8) * 2;
#pragma unroll
        for (int mt = 0; mt < MT; mt++) {
            uint32_t off = sw128((uint32_t)(warpM + mt * 16 + arow) * 128 + acol);
            ldsm_x4(ah[mt][0], ah[mt][1], ah[mt][2], ah[mt][3], aHi + off);
            ldsm_x4(al[mt][0], al[mt][1], al[mt][2], al[mt][3], aLo + off);
        }
#pragma unroll
        for (int mt = 0; mt < MT; mt++)
#pragma unroll
            for (int nt = 0; nt < NT; nt++)
                mma16816(acc[mt][nt], ah[mt][0], ah[mt][1], ah[mt][2], ah[mt][3],
                         bh[nt][0], bh[nt][1]);
#pragma unroll
        for (int mt = 0; mt < MT; mt++)
#pragma unroll
            for (int nt = 0; nt < NT; nt++)
                mma16816(acc[mt][nt], ah[mt][0], ah[mt][1], ah[mt][2], ah[mt][3],
                         bl[nt][0], bl[nt][1]);
#pragma unroll
        for (int mt = 0; mt < MT; mt++)
#pragma unroll
            for (int nt = 0; nt < NT; nt++)
                mma16816(acc[mt][nt], al[mt][0], al[mt][1], al[mt][2], al[mt][3],
                         bh[nt][0], bh[nt][1]);
    }
}

// ---------------------------------------------------------------------------
// Fused fp32 -> bf16 hi/lo split for all 7 tensors (one launch)
// ---------------------------------------------------------------------------
__global__ void cvt_all(const float* __restrict__ s0, const float* __restrict__ s1,
                        const float* __restrict__ s2, const float* __restrict__ s3,
                        const float* __restrict__ s4, const float* __restrict__ s5,
                        const float* __restrict__ s6,
                        __nv_bfloat16* __restrict__ h0, __nv_bfloat16* __restrict__ l0,
                        __nv_bfloat16* __restrict__ h1, __nv_bfloat16* __restrict__ l1,
                        __nv_bfloat16* __restrict__ h2, __nv_bfloat16* __restrict__ l2,
                        __nv_bfloat16* __restrict__ h3, __nv_bfloat16* __restrict__ l3,
                        __nv_bfloat16* __restrict__ h4, __nv_bfloat16* __restrict__ l4,
                        __nv_bfloat16* __restrict__ h5, __nv_bfloat16* __restrict__ l5,
                        __nv_bfloat16* __restrict__ h6, __nv_bfloat16* __restrict__ l6,
                        int na4, int nw4)
{
    const int total = 3 * na4 + 4 * nw4;
    for (int i = blockIdx.x * blockDim.x + threadIdx.x; i < total;
         i += gridDim.x * blockDim.x) {
        const float* src; __nv_bfloat16* hh; __nv_bfloat16* ll; int j;
        if (i < na4)          { src = s0; hh = h0; ll = l0; j = i; }
        else if (i < 2 * na4) { src = s1; hh = h1; ll = l1; j = i - na4; }
        else if (i < 3 * na4) { src = s2; hh = h2; ll = l2; j = i - 2 * na4; }
        else {
            int k = i - 3 * na4;
            if (k < nw4)          { src = s3; hh = h3; ll = l3; j = k; }
            else if (k < 2 * nw4) { src = s4; hh = h4; ll = l4; j = k - nw4; }
            else if (k < 3 * nw4) { src = s5; hh = h5; ll = l5; j = k - 2 * nw4; }
            else                  { src = s6; hh = h6; ll = l6; j = k - 3 * nw4; }
        }
        float4 v = ((const float4*)src)[j];
        __nv_bfloat16 hx = __float2bfloat16(v.x), hy = __float2bfloat16(v.y);
        __nv_bfloat16 hz = __float2bfloat16(v.z), hw = __float2bfloat16(v.w);
        ((uint2*)hh)[j] = make_uint2(bf2u(hx, hy), bf2u(hz, hw));
        ((uint2*)ll)[j] = make_uint2(
            packf_hi(v.x - __bfloat162float(hx), v.y - __bfloat162float(hy)),
            packf_hi(v.z - __bfloat162float(hz), v.w - __bfloat162float(hw)));
    }
}

// ---------------------------------------------------------------------------
// Merged Q/K/V projection GEMM: grid.z selects weight set / output.
// ---------------------------------------------------------------------------
__global__ __launch_bounds__(256)
void qkv_hmma(const __nv_bfloat16* __restrict__ Aqh, const __nv_bfloat16* __restrict__ Aql,
              const __nv_bfloat16* __restrict__ Akh, const __nv_bfloat16* __restrict__ Akl,
              const __nv_bfloat16* __restrict__ Avh, const __nv_bfloat16* __restrict__ Avl,
              const __nv_bfloat16* __restrict__ Wqh, const __nv_bfloat16* __restrict__ Wql,
              const __nv_bfloat16* __restrict__ Wkh, const __nv_bfloat16* __restrict__ Wkl,
              const __nv_bfloat16* __restrict__ Wvh, const __nv_bfloat16* __restrict__ Wvl,
              const float* __restrict__ bq, const float* __restrict__ bk,
              const float* __restrict__ bv,
              __nv_bfloat16* __restrict__ Qh, __nv_bfloat16* __restrict__ Ql,
              __nv_bfloat16* __restrict__ Kh, __nv_bfloat16* __restrict__ Kl,
              __nv_bfloat16* __restrict__ Vth, __nv_bfloat16* __restrict__ Vtl,
              int N, int K, int vt_stride)
{
    extern __shared__ char smem[];
    const uint32_t sb = smem_u32(smem);
    const uint32_t tb = (sb + 1023) & ~1023u;
    const uint32_t AH = 0, AL = 16384, BH = 32768, BL = 49152;

    const int z = blockIdx.z;
    const __nv_bfloat16 *Ah, *Al, *Bh, *Bl;
    const float* bias;
    __nv_bfloat16 *Ch, *Cl;
    if (z == 0)      { Ah = Aqh; Al = Aql; Bh = Wqh; Bl = Wql; bias = bq; Ch = Qh;  Cl = Ql;  }
    else if (z == 1) { Ah = Akh; Al = Akl; Bh = Wkh; Bl = Wkl; bias = bk; Ch = Kh;  Cl = Kl;  }
    else             { Ah = Avh; Al = Avl; Bh = Wvh; Bl = Wvl; bias = bv; Ch = Vth; Cl = Vtl; }

    const int tid = threadIdx.x, wid = tid >> 5, lane = tid & 31;
    const int m0 = blockIdx.y * 128, n0 = blockIdx.x * 128;
    const int warpM = (wid >> 2) * 64, warpN = (wid & 3) * 32;

    float acc[4][4][4];
#pragma unroll
    for (int a = 0; a < 4; a++)
#pragma unroll
        for (int b = 0; b < 4; b++)
#pragma unroll
            for (int c = 0; c < 4; c++) acc[a][b][c] = 0.f;

    const int lrow = tid >> 1, qb = (tid & 1) * 4;
    const int nc = K >> 6;

    auto load_chunk = [&](int c, int b) {
        const uint32_t buf = tb + (uint32_t)b * 65536;
        const size_t aoff = (size_t)(m0 + lrow) * K + c * 64;
        const size_t boff = (size_t)(n0 + lrow) * K + c * 64;
#pragma unroll
        for (int j = 0; j < 4; j++) {
            const int q = qb + j;
            const uint32_t so = sw128((uint32_t)lrow * 128 + q * 16);
            cp16(buf + AH + so, Ah + aoff + q * 8);
            cp16(buf + AL + so, Al + aoff + q * 8);
            cp16(buf + BH + so, Bh + boff + q * 8);
            cp16(buf + BL + so, Bl + boff + q * 8);
        }
        asm volatile("cp.async.commit_group;" ::: "memory");
    };

    load_chunk(0, 0);
    for (int c = 0; c < nc; c++) {
        if (c + 1 < nc) {
            load_chunk(c + 1, (c + 1) & 1);
            asm volatile("cp.async.wait_group 1;" ::: "memory");
        } else {
            asm volatile("cp.async.wait_group 0;" ::: "memory");
        }
        __syncthreads();
        const uint32_t buf = tb + (uint32_t)(c & 1) * 65536;
        compute_chunk<4, 4>(buf + AH, buf + AL, buf + BH, buf + BL, warpM, warpN, lane, acc);
        __syncthreads();
    }

    const int r0 = lane >> 2, cj = (lane & 3) * 2;
#pragma unroll
    for (int mt = 0; mt < 4; mt++) {
#pragma unroll
        for (int nt = 0; nt < 4; nt++) {
            const int m = m0 + warpM + mt * 16 + r0;
            const int n = n0 + warpN + nt * 8 + cj;
            const float* cc = acc[mt][nt];
            float b0 = __ldg(bias + n), b1 = __ldg(bias + n + 1);
            float v0 = cc[0] + b0, v1 = cc[1] + b1, v2 = cc[2] + b0, v3 = cc[3] + b1;
            if (z < 2) {
                __nv_bfloat16 h0 = __float2bfloat16(v0), h1 = __float2bfloat16(v1);
                __nv_bfloat16 h2 = __float2bfloat16(v2), h3 = __float2bfloat16(v3);
                *(uint32_t*)(Ch + (size_t)m * N + n)       = bf2u(h0, h1);
                *(uint32_t*)(Ch + (size_t)(m + 8) * N + n) = bf2u(h2, h3);
                *(uint32_t*)(Cl + (size_t)m * N + n) =
                    packf_hi(v0 - __bfloat162float(h0), v1 - __bfloat162float(h1));
                *(uint32_t*)(Cl + (size_t)(m + 8) * N + n) =
                    packf_hi(v2 - __bfloat162float(h2), v3 - __bfloat162float(h3));
            } else {
                float v[4] = {v0, v1, v2, v3};
                int mm[4] = {m, m, m + 8, m + 8};
                int nn[4] = {n, n + 1, n, n + 1};
#pragma unroll
                for (int e = 0; e < 4; e++) {
                    __nv_bfloat16 hh = __float2bfloat16(v[e]);
                    Ch[(size_t)nn[e] * vt_stride + mm[e]] = hh;
                    Cl[(size_t)nn[e] * vt_stride + mm[e]] =
                        __float2bfloat16(v[e] - __bfloat162float(hh));
                }
            }
        }
    }
}

// ---------------------------------------------------------------------------
// FC GEMM (fp32 out)
// ---------------------------------------------------------------------------
__global__ __launch_bounds__(256)
void fc_hmma(const __nv_bfloat16* __restrict__ Ah, const __nv_bfloat16* __restrict__ Al,
             const __nv_bfloat16* __restrict__ Bh, const __nv_bfloat16* __restrict__ Bl,
             const float* __restrict__ bias, float* __restrict__ Cf, int N, int K)
{
    extern __shared__ char smem[];
    const uint32_t sb = smem_u32(smem);
    const uint32_t tb = (sb + 1023) & ~1023u;
    const uint32_t AH = 0, AL = 16384, BH = 32768, BL = 49152;

    const int tid = threadIdx.x, wid = tid >> 5, lane = tid & 31;
    const int m0 = blockIdx.y * 128, n0 = blockIdx.x * 128;
    const int warpM = (wid >> 2) * 64, warpN = (wid & 3) * 32;

    float acc[4][4][4];
#pragma unroll
    for (int a = 0; a < 4; a++)
#pragma unroll
        for (int b = 0; b < 4; b++)
#pragma unroll
            for (int c = 0; c < 4; c++) acc[a][b][c] = 0.f;

    const int lrow = tid >> 1, qb = (tid & 1) * 4;
    const int nc = K >> 6;

    auto load_chunk = [&](int c, int b) {
        const uint32_t buf = tb + (uint32_t)b * 65536;
        const size_t aoff = (size_t)(m0 + lrow) * K + c * 64;
        const size_t boff = (size_t)(n0 + lrow) * K + c * 64;
#pragma unroll
        for (int j = 0; j < 4; j++) {
            const int q = qb + j;
            const uint32_t so = sw128((uint32_t)lrow * 128 + q * 16);
            cp16(buf + AH + so, Ah + aoff + q * 8);
            cp16(buf + AL + so, Al + aoff + q * 8);
            cp16(buf + BH + so, Bh + boff + q * 8);
            cp16(buf + BL + so, Bl + boff + q * 8);
        }
        asm volatile("cp.async.commit_group;" ::: "memory");
    };

    load_chunk(0, 0);
    for (int c = 0; c < nc; c++) {
        if (c + 1 < nc) {
            load_chunk(c + 1, (c + 1) & 1);
            asm volatile("cp.async.wait_group 1;" ::: "memory");
        } else {
            asm volatile("cp.async.wait_group 0;" ::: "memory");
        }
        __syncthreads();
        const uint32_t buf = tb + (uint32_t)(c & 1) * 65536;
        compute_chunk<4, 4>(buf + AH, buf + AL, buf + BH, buf + BL, warpM, warpN, lane, acc);
        __syncthreads();
    }

    const int r0 = lane >> 2, cj = (lane & 3) * 2;
#pragma unroll
    for (int mt = 0; mt < 4; mt++) {
#pragma unroll
        for (int nt = 0; nt < 4; nt++) {
            const int m = m0 + warpM + mt * 16 + r0;
            const int n = n0 + warpN + nt * 8 + cj;
            const float* cc = acc[mt][nt];
            float b0 = __ldg(bias + n), b1 = __ldg(bias + n + 1);
            *(float2*)(Cf + (size_t)m * N + n)       = make_float2(cc[0] + b0, cc[1] + b1);
            *(float2*)(Cf + (size_t)(m + 8) * N + n) = make_float2(cc[2] + b0, cc[3] + b1);
        }
    }
}

// ---------------------------------------------------------------------------
// Scores: attn[h][m][n] = 0.125 * QK (raw). grid (S/128, L/128, H)
// ---------------------------------------------------------------------------
__global__ __launch_bounds__(256)
void scores_hmma(const __nv_bfloat16* __restrict__ Qh, const __nv_bfloat16* __restrict__ Ql,
                 const __nv_bfloat16* __restrict__ Kh, const __nv_bfloat16* __restrict__ Kl,
                 float* __restrict__ attn, int L, int S)
{
    extern __shared__ char smem[];
    const uint32_t sb = smem_u32(smem);
    const uint32_t tb = (sb + 1023) & ~1023u;
    char* tile = smem + (tb - sb);
    const uint32_t AH = 0, AL = 16384, BH = 32768, BL = 49152;

    const int tid = threadIdx.x, wid = tid >> 5, lane = tid & 31;
    const int n0 = blockIdx.x * 128, m0 = blockIdx.y * 128, h = blockIdx.z;
    const int warpM = (wid >> 2) * 64, warpN = (wid & 3) * 32;

    const int lrow = tid >> 1, qb = (tid & 1) * 4;
    const size_t qoff = (size_t)(m0 + lrow) * E_DIM + h * D_HEAD;
    const size_t koff = (size_t)(n0 + lrow) * E_DIM + h * D_HEAD;
#pragma unroll
    for (int j = 0; j < 4; j++) {
        const int q = qb + j;
        const uint32_t so = sw128((uint32_t)lrow * 128 + q * 16);
        *(uint4*)(tile + AH + so) = *(const uint4*)(Qh + qoff + q * 8);
        *(uint4*)(tile + AL + so) = *(const uint4*)(Ql + qoff + q * 8);
        *(uint4*)(tile + BH + so) = *(const uint4*)(Kh + koff + q * 8);
        *(uint4*)(tile + BL + so) = *(const uint4*)(Kl + koff + q * 8);
    }
    __syncthreads();

    float acc[4][4][4];
#pragma unroll
    for (int a = 0; a < 4; a++)
#pragma unroll
        for (int b = 0; b < 4; b++)
#pragma unroll
            for (int c = 0; c < 4; c++) acc[a][b][c] = 0.f;

    compute_chunk<4, 4>(tb + AH, tb + AL, tb + BH, tb + BL, warpM, warpN, lane, acc);

    const int r0 = lane >> 2, cj = (lane & 3) * 2;
#pragma unroll
    for (int mt = 0; mt < 4; mt++) {
#pragma unroll
        for (int nt = 0; nt < 4; nt++) {
            const int m = m0 + warpM + mt * 16 + r0;
            const int n = n0 + warpN + nt * 8 + cj;
            const float* cc = acc[mt][nt];
            *(float2*)(attn + ((size_t)h * L + m) * S + n) =
                make_float2(cc[0] * 0.125f, cc[1] * 0.125f);
            *(float2*)(attn + ((size_t)h * L + m + 8) * S + n) =
                make_float2(cc[2] * 0.125f, cc[3] * 0.125f);
        }
    }
}

// ---------------------------------------------------------------------------
// Fused softmax + PV. Each block owns rows [m0,m0+128) of head h and the full
// row extent, so row sums are block-local (pass 1), then pass 2 normalizes,
// writes the final attn weights in place, and feeds the MMA. grid (L/128, H).
// ---------------------------------------------------------------------------
__global__ __launch_bounds__(256)
void pv_hmma(float* __restrict__ attn,
             const __nv_bfloat16* __restrict__ Vth, const __nv_bfloat16* __restrict__ Vtl,
             __nv_bfloat16* __restrict__ Oh, __nv_bfloat16* __restrict__ Ol,
             const int* __restrict__ causal_flag, int L, int S)
{
    extern __shared__ char smem[];
    const uint32_t sb = smem_u32(smem);
    const uint32_t tb = (sb + 1023) & ~1023u;
    char* tile = smem + (tb - sb);
    const uint32_t PH = 0, PL = 16384, VH = 32768, VL = 40960;

    const int tid = threadIdx.x, wid = tid >> 5, lane = tid & 31;
    const int m0 = blockIdx.x * 128, h = blockIdx.y;
    const int warpM = (wid >> 1) * 32, warpN = (wid & 1) * 32;

    const int prow = tid >> 1, phalf = tid & 1;
    const int grow = m0 + prow;
    const bool causal = (*causal_flag) != 0;
    float* rowbase = attn + ((size_t)h * L + grow) * S + phalf * 32;

    // ---- pass 1: row sum of exp (block-local, no atomics) ----
    float ssum = 0.f;
    for (int c = 0; c < (S >> 6); c++) {
        const float4* ps = (const float4*)(rowbase + c * 64);
#pragma unroll
        for (int j = 0; j < 8; j++) {
            float4 v = ps[j];
            float e0 = __expf(v.x), e1 = __expf(v.y), e2 = __expf(v.z), e3 = __expf(v.w);
            if (causal) {
                const int s0 = c * 64 + phalf * 32 + j * 4;
                if (s0 + 0 > grow) e0 = 0.f;
                if (s0 + 1 > grow) e1 = 0.f;
                if (s0 + 2 > grow) e2 = 0.f;
                if (s0 + 3 > grow) e3 = 0.f;
            }
            ssum += e0 + e1 + e2 + e3;
        }
    }
    // threads tid and tid^1 share the same row (adjacent lanes)
    ssum += __shfl_xor_sync(0xffffffffu, ssum, 1);
    const float inv = 1.0f / ssum;

    float acc[2][4][4];
#pragma unroll
    for (int a = 0; a < 2; a++)
#pragma unroll
        for (int b = 0; b < 4; b++)
#pragma unroll
            for (int c = 0; c < 4; c++) acc[a][b][c] = 0.f;

    const int vrow = tid >> 2, vq = tid & 3;

    // ---- pass 2: normalize (write final weights), hi/lo split, MMA ----
    for (int c = 0; c < (S >> 6); c++) {
        float4* psrc = (float4*)(rowbase + c * 64);
#pragma unroll
        for (int j = 0; j < 8; j++) {
            float4 v = psrc[j];
            float p0 = __expf(v.x) * inv, p1 = __expf(v.y) * inv;
            float p2 = __expf(v.z) * inv, p3 = __expf(v.w) * inv;
            if (causal) {
                const int s0 = c * 64 + phalf * 32 + j * 4;
                if (s0 + 0 > grow) p0 = 0.f;
                if (s0 + 1 > grow) p1 = 0.f;
                if (s0 + 2 > grow) p2 = 0.f;
                if (s0 + 3 > grow) p3 = 0.f;
            }
            psrc[j] = make_float4(p0, p1, p2, p3);   // final attn weights out
            __nv_bfloat16 hx = __float2bfloat16(p0), hy = __float2bfloat16(p1);
            __nv_bfloat16 hz = __float2bfloat16(p2), hw = __float2bfloat16(p3);
            const uint32_t so = sw128((uint32_t)prow * 128 + phalf * 64 + j * 8);
            *(uint2*)(tile + PH + so) = make_uint2(bf2u(hx, hy), bf2u(hz, hw));
            *(uint2*)(tile + PL + so) = make_uint2(
                packf_hi(p0 - __bfloat162float(hx), p1 - __bfloat162float(hy)),
                packf_hi(p2 - __bfloat162float(hz), p3 - __bfloat162float(hw)));
        }
        const size_t vo = (size_t)(h * 64 + vrow) * S + c * 64;
#pragma unroll
        for (int jj = 0; jj < 2; jj++) {
            const int q = vq + jj * 4;
            const uint32_t so = sw128((uint32_t)vrow * 128 + q * 16);
            *(uint4*)(tile + VH + so) = *(const uint4*)(Vth + vo + q * 8);
            *(uint4*)(tile + VL + so) = *(const uint4*)(Vtl + vo + q * 8);
        }
        __syncthreads();
        compute_chunk<2, 4>(tb + PH, tb + PL, tb + VH, tb + VL, warpM, warpN, lane, acc);
        __syncthreads();
    }

    const int r0 = lane >> 2, cj = (lane & 3) * 2;
#pragma unroll
    for (int mt = 0; mt < 2; mt++) {
#pragma unroll
        for (int nt = 0; nt < 4; nt++) {
            const int m = m0 + warpM + mt * 16 + r0;
            const int n = h * 64 + warpN + nt * 8 + cj;
            const float* cc = acc[mt][nt];
            __nv_bfloat16 h0b = __float2bfloat16(cc[0]), h1b = __float2bfloat16(cc[1]);
            __nv_bfloat16 h2b = __float2bfloat16(cc[2]), h3b = __float2bfloat16(cc[3]);
            *(uint32_t*)(Oh + (size_t)m * E_DIM + n)       = bf2u(h0b, h1b);
            *(uint32_t*)(Oh + (size_t)(m + 8) * E_DIM + n) = bf2u(h2b, h3b);
            *(uint32_t*)(Ol + (size_t)m * E_DIM + n) =
                packf_hi(cc[0] - __bfloat162float(h0b), cc[1] - __bfloat162float(h1b));
            *(uint32_t*)(Ol + (size_t)(m + 8) * E_DIM + n) =
                packf_hi(cc[2] - __bfloat162float(h2b), cc[3] - __bfloat162float(h3b));
        }
    }
}

// ---------------------------------------------------------------------------
// Launch
// ---------------------------------------------------------------------------
extern "C" void kernel_launch(void* const* d_in, const int* in_sizes, int n_in,
                              void* d_out, int out_size)
{
    const float* query = (const float*)d_in[0];
    const float* key   = (const float*)d_in[1];
    const float* value = (const float*)d_in[2];
    const float* wq_w  = (const float*)d_in[3];
    const float* wq_b  = (const float*)d_in[4];
    const float* wk_w  = (const float*)d_in[5];
    const float* wk_b  = (const float*)d_in[6];
    const float* wv_w  = (const float*)d_in[7];
    const float* wv_b  = (const float*)d_in[8];
    const float* fc_w  = (const float*)d_in[9];
    const float* fc_b  = (const float*)d_in[10];
    const int* causal  = (const int*)d_in[11];

    const int L = in_sizes[0] / E_DIM;
    const int S = in_sizes[1] / E_DIM;

    float* out = (float*)d_out;
    float* attn_ptr;
    {
        size_t need = (size_t)L * E_DIM + (size_t)H_HEADS * L * S;
        if ((size_t)out_size >= need) attn_ptr = out + (size_t)L * E_DIM;
        else cudaGetSymbolAddress((void**)&attn_ptr, g_attn_fb);
    }

    __nv_bfloat16 *xqh, *xql, *xkh, *xkl, *xvh, *xvl;
    __nv_bfloat16 *wqh, *wql, *wkh, *wkl, *wvh, *wvl, *fch, *fcl;
    __nv_bfloat16 *qh, *ql, *kh, *kl, *vth, *vtl, *oh, *ol;
    cudaGetSymbolAddress((void**)&xqh, g_xq_h); cudaGetSymbolAddress((void**)&xql, g_xq_l);
    cudaGetSymbolAddress((void**)&xkh, g_xk_h); cudaGetSymbolAddress((void**)&xkl, g_xk_l);
    cudaGetSymbolAddress((void**)&xvh, g_xv_h); cudaGetSymbolAddress((void**)&xvl, g_xv_l);
    cudaGetSymbolAddress((void**)&wqh, g_wq_h); cudaGetSymbolAddress((void**)&wql, g_wq_l);
    cudaGetSymbolAddress((void**)&wkh, g_wk_h); cudaGetSymbolAddress((void**)&wkl, g_wk_l);
    cudaGetSymbolAddress((void**)&wvh, g_wv_h); cudaGetSymbolAddress((void**)&wvl, g_wv_l);
    cudaGetSymbolAddress((void**)&fch, g_fc_h); cudaGetSymbolAddress((void**)&fcl, g_fc_l);
    cudaGetSymbolAddress((void**)&qh, g_q_h);   cudaGetSymbolAddress((void**)&ql, g_q_l);
    cudaGetSymbolAddress((void**)&kh, g_k_h);   cudaGetSymbolAddress((void**)&kl, g_k_l);
    cudaGetSymbolAddress((void**)&vth, g_vt_h); cudaGetSymbolAddress((void**)&vtl, g_vt_l);
    cudaGetSymbolAddress((void**)&oh, g_o_h);   cudaGetSymbolAddress((void**)&ol, g_o_l);

    const int GEMM_SMEM   = 1024 + 2 * 65536;
    const int SCORES_SMEM = 1024 + 65536;
    const int PV_SMEM     = 1024 + 49152;
    cudaFuncSetAttribute(qkv_hmma,    cudaFuncAttributeMaxDynamicSharedMemorySize, GEMM_SMEM);
    cudaFuncSetAttribute(fc_hmma,     cudaFuncAttributeMaxDynamicSharedMemorySize, GEMM_SMEM);
    cudaFuncSetAttribute(scores_hmma, cudaFuncAttributeMaxDynamicSharedMemorySize, SCORES_SMEM);
    cudaFuncSetAttribute(pv_hmma,     cudaFuncAttributeMaxDynamicSharedMemorySize, PV_SMEM);

    // launch 0: all hi/lo conversions fused
    {
        const int na4 = (L * E_DIM) / 4, nw4 = (E_DIM * E_DIM) / 4;
        cvt_all<<<1024, 256>>>(query, key, value, wq_w, wk_w, wv_w, fc_w,
                               xqh, xql, xkh, xkl, xvh, xvl,
                               wqh, wql, wkh, wkl, wvh, wvl, fch, fcl,
                               na4, nw4);
    }

    // launch 1: Q/K/V projections merged
    {
        dim3 grid(E_DIM / 128, L / 128, 3);
        qkv_hmma<<<grid, 256, GEMM_SMEM>>>(
            xqh, xql, xkh, xkl, xvh, xvl,
            wqh, wql, wkh, wkl, wvh, wvl,
            wq_b, wk_b, wv_b,
            qh, ql, kh, kl, vth, vtl,
            E_DIM, E_DIM, S);
    }

    // launch 2: scores (raw, scaled)
    {
        dim3 grid(S / 128, L / 128, H_HEADS);
        scores_hmma<<<grid, 256, SCORES_SMEM>>>(qh, ql, kh, kl, attn_ptr, L, S);
    }

    // launch 3: fused softmax + PV (writes final attn weights + O)
    {
        dim3 grid(L / 128, H_HEADS);
        pv_hmma<<<grid, 256, PV_SMEM>>>(attn_ptr, vth, vtl, oh, ol, causal, L, S);
    }

    // launch 4: FC
    {
        dim3 grid(E_DIM / 128, L / 128);
        fc_hmma<<<grid, 256, GEMM_SMEM>>>(oh, ol, fch, fcl, fc_b, out, E_DIM, E_DIM);
    }
}

// round 13
// speedup vs baseline: 1.1383x; 1.1383x over previous
#include <cuda_runtime.h>
#include <cuda_bf16.h>
#include <stdint.h>
#include <math.h>

#define E_DIM 1024
#define H_HEADS 16
#define D_HEAD 64
#define L_MAX 4096

// ---------------------------------------------------------------------------
// Device scratch (allocation-free kernel_launch)
// ---------------------------------------------------------------------------
__device__ __nv_bfloat16 g_xq_h[L_MAX * E_DIM], g_xq_l[L_MAX * E_DIM];
__device__ __nv_bfloat16 g_xk_h[L_MAX * E_DIM], g_xk_l[L_MAX * E_DIM];
__device__ __nv_bfloat16 g_xv_h[L_MAX * E_DIM], g_xv_l[L_MAX * E_DIM];
__device__ __nv_bfloat16 g_wq_h[E_DIM * E_DIM], g_wq_l[E_DIM * E_DIM];
__device__ __nv_bfloat16 g_wk_h[E_DIM * E_DIM], g_wk_l[E_DIM * E_DIM];
__device__ __nv_bfloat16 g_wv_h[E_DIM * E_DIM], g_wv_l[E_DIM * E_DIM];
__device__ __nv_bfloat16 g_fc_h[E_DIM * E_DIM], g_fc_l[E_DIM * E_DIM];
__device__ __nv_bfloat16 g_q_h[L_MAX * E_DIM], g_q_l[L_MAX * E_DIM];
__device__ __nv_bfloat16 g_k_h[L_MAX * E_DIM], g_k_l[L_MAX * E_DIM];
__device__ __nv_bfloat16 g_vt_h[E_DIM * L_MAX], g_vt_l[E_DIM * L_MAX];   // [E][S]
__device__ __nv_bfloat16 g_o_h[L_MAX * E_DIM], g_o_l[L_MAX * E_DIM];
__device__ float g_attn_fb[(size_t)H_HEADS * L_MAX * L_MAX];

#define DINLINE __device__ __forceinline__

DINLINE uint32_t smem_u32(const void* p) {
    uint32_t a;
    asm("{ .reg .u64 t; cvta.to.shared.u64 t, %1; cvt.u32.u64 %0, t; }" : "=r"(a) : "l"(p));
    return a;
}
DINLINE uint32_t sw128(uint32_t off) { return off ^ ((off >> 3) & 0x70); }

DINLINE void ldsm_x4(uint32_t& r0, uint32_t& r1, uint32_t& r2, uint32_t& r3, uint32_t addr) {
    asm volatile("ldmatrix.sync.aligned.m8n8.x4.shared.b16 {%0,%1,%2,%3}, [%4];"
                 : "=r"(r0), "=r"(r1), "=r"(r2), "=r"(r3) : "r"(addr));
}
DINLINE void ldsm_x2(uint32_t& r0, uint32_t& r1, uint32_t addr) {
    asm volatile("ldmatrix.sync.aligned.m8n8.x2.shared.b16 {%0,%1}, [%2];"
                 : "=r"(r0), "=r"(r1) : "r"(addr));
}
DINLINE void mma16816(float c[4], uint32_t a0, uint32_t a1, uint32_t a2, uint32_t a3,
                      uint32_t b0, uint32_t b1) {
    asm volatile(
        "mma.sync.aligned.m16n8k16.row.col.f32.bf16.bf16.f32 "
        "{%0,%1,%2,%3}, {%4,%5,%6,%7}, {%8,%9}, {%0,%1,%2,%3};"
        : "+f"(c[0]), "+f"(c[1]), "+f"(c[2]), "+f"(c[3])
        : "r"(a0), "r"(a1), "r"(a2), "r"(a3), "r"(b0), "r"(b1));
}
DINLINE void cp16(uint32_t dst, const void* src) {
    asm volatile("cp.async.ca.shared.global [%0], [%1], 16;" :: "r"(dst), "l"(src));
}

DINLINE uint32_t bf2u(__nv_bfloat16 a, __nv_bfloat16 b) {
    __nv_bfloat162 t = __halves2bfloat162(a, b);
    return *reinterpret_cast<uint32_t*>(&t);
}
DINLINE uint32_t packf_hi(float a, float b) {
    return bf2u(__float2bfloat16(a), __float2bfloat16(b));
}

// ---------------------------------------------------------------------------
// Core: one KC=64 chunk, bf16x3 emulated fp32 (hi*hi + hi*lo + lo*hi).
// ---------------------------------------------------------------------------
template<int MT, int NT>
DINLINE void compute_chunk(uint32_t aHi, uint32_t aLo, uint32_t bHi, uint32_t bLo,
                           int warpM, int warpN, int lane, float (&acc)[MT][NT][4])
{
    const int arow = lane & 15, asel = lane >> 4;
    const int brow = lane & 7,  bsel = (lane >> 3) & 1;
#pragma unroll
    for (int ks = 0; ks < 4; ks++) {
        uint32_t bh[NT][2], bl[NT][2];
        uint32_t ah[MT][4], al[MT][4];
        const uint32_t bcol = (uint32_t)(ks * 16 + bsel * 8) * 2;
#pragma unroll
        for (int nt = 0; nt < NT; nt++) {
            uint32_t off = sw128((uint32_t)(warpN + nt * 8 + brow) * 128 + bcol);
            ldsm_x2(bh[nt][0], bh[nt][1], bHi + off);
            ldsm_x2(bl[nt][0], bl[nt][1], bLo + off);
        }
        const uint32_t acol = (uint32_t)(ks * 16 + asel * 8) * 2;
#pragma unroll
        for (int mt = 0; mt < MT; mt++) {
            uint32_t off = sw128((uint32_t)(warpM + mt * 16 + arow) * 128 + acol);
            ldsm_x4(ah[mt][0], ah[mt][1], ah[mt][2], ah[mt][3], aHi + off);
            ldsm_x4(al[mt][0], al[mt][1], al[mt][2], al[mt][3], aLo + off);
        }
#pragma unroll
        for (int mt = 0; mt < MT; mt++)
#pragma unroll
            for (int nt = 0; nt < NT; nt++)
                mma16816(acc[mt][nt], ah[mt][0], ah[mt][1], ah[mt][2], ah[mt][3],
                         bh[nt][0], bh[nt][1]);
#pragma unroll
        for (int mt = 0; mt < MT; mt++)
#pragma unroll
            for (int nt = 0; nt < NT; nt++)
                mma16816(acc[mt][nt], ah[mt][0], ah[mt][1], ah[mt][2], ah[mt][3],
                         bl[nt][0], bl[nt][1]);
#pragma unroll
        for (int mt = 0; mt < MT; mt++)
#pragma unroll
            for (int nt = 0; nt < NT; nt++)
                mma16816(acc[mt][nt], al[mt][0], al[mt][1], al[mt][2], al[mt][3],
                         bh[nt][0], bh[nt][1]);
    }
}

// ---------------------------------------------------------------------------
// Fused fp32 -> bf16 hi/lo split for all 7 tensors (one launch)
// ---------------------------------------------------------------------------
__global__ void cvt_all(const float* __restrict__ s0, const float* __restrict__ s1,
                        const float* __restrict__ s2, const float* __restrict__ s3,
                        const float* __restrict__ s4, const float* __restrict__ s5,
                        const float* __restrict__ s6,
                        __nv_bfloat16* __restrict__ h0, __nv_bfloat16* __restrict__ l0,
                        __nv_bfloat16* __restrict__ h1, __nv_bfloat16* __restrict__ l1,
                        __nv_bfloat16* __restrict__ h2, __nv_bfloat16* __restrict__ l2,
                        __nv_bfloat16* __restrict__ h3, __nv_bfloat16* __restrict__ l3,
                        __nv_bfloat16* __restrict__ h4, __nv_bfloat16* __restrict__ l4,
                        __nv_bfloat16* __restrict__ h5, __nv_bfloat16* __restrict__ l5,
                        __nv_bfloat16* __restrict__ h6, __nv_bfloat16* __restrict__ l6,
                        int na4, int nw4)
{
    const int total = 3 * na4 + 4 * nw4;
    for (int i = blockIdx.x * blockDim.x + threadIdx.x; i < total;
         i += gridDim.x * blockDim.x) {
        const float* src; __nv_bfloat16* hh; __nv_bfloat16* ll; int j;
        if (i < na4)          { src = s0; hh = h0; ll = l0; j = i; }
        else if (i < 2 * na4) { src = s1; hh = h1; ll = l1; j = i - na4; }
        else if (i < 3 * na4) { src = s2; hh = h2; ll = l2; j = i - 2 * na4; }
        else {
            int k = i - 3 * na4;
            if (k < nw4)          { src = s3; hh = h3; ll = l3; j = k; }
            else if (k < 2 * nw4) { src = s4; hh = h4; ll = l4; j = k - nw4; }
            else if (k < 3 * nw4) { src = s5; hh = h5; ll = l5; j = k - 2 * nw4; }
            else                  { src = s6; hh = h6; ll = l6; j = k - 3 * nw4; }
        }
        float4 v = ((const float4*)src)[j];
        __nv_bfloat16 hx = __float2bfloat16(v.x), hy = __float2bfloat16(v.y);
        __nv_bfloat16 hz = __float2bfloat16(v.z), hw = __float2bfloat16(v.w);
        ((uint2*)hh)[j] = make_uint2(bf2u(hx, hy), bf2u(hz, hw));
        ((uint2*)ll)[j] = make_uint2(
            packf_hi(v.x - __bfloat162float(hx), v.y - __bfloat162float(hy)),
            packf_hi(v.z - __bfloat162float(hz), v.w - __bfloat162float(hw)));
    }
}

// ---------------------------------------------------------------------------
// Merged Q/K/V projection GEMM: grid.z selects weight set / output.
// ---------------------------------------------------------------------------
__global__ __launch_bounds__(256)
void qkv_hmma(const __nv_bfloat16* __restrict__ Aqh, const __nv_bfloat16* __restrict__ Aql,
              const __nv_bfloat16* __restrict__ Akh, const __nv_bfloat16* __restrict__ Akl,
              const __nv_bfloat16* __restrict__ Avh, const __nv_bfloat16* __restrict__ Avl,
              const __nv_bfloat16* __restrict__ Wqh, const __nv_bfloat16* __restrict__ Wql,
              const __nv_bfloat16* __restrict__ Wkh, const __nv_bfloat16* __restrict__ Wkl,
              const __nv_bfloat16* __restrict__ Wvh, const __nv_bfloat16* __restrict__ Wvl,
              const float* __restrict__ bq, const float* __restrict__ bk,
              const float* __restrict__ bv,
              __nv_bfloat16* __restrict__ Qh, __nv_bfloat16* __restrict__ Ql,
              __nv_bfloat16* __restrict__ Kh, __nv_bfloat16* __restrict__ Kl,
              __nv_bfloat16* __restrict__ Vth, __nv_bfloat16* __restrict__ Vtl,
              int N, int K, int vt_stride)
{
    extern __shared__ char smem[];
    const uint32_t sb = smem_u32(smem);
    const uint32_t tb = (sb + 1023) & ~1023u;
    const uint32_t AH = 0, AL = 16384, BH = 32768, BL = 49152;

    const int z = blockIdx.z;
    const __nv_bfloat16 *Ah, *Al, *Bh, *Bl;
    const float* bias;
    __nv_bfloat16 *Ch, *Cl;
    if (z == 0)      { Ah = Aqh; Al = Aql; Bh = Wqh; Bl = Wql; bias = bq; Ch = Qh;  Cl = Ql;  }
    else if (z == 1) { Ah = Akh; Al = Akl; Bh = Wkh; Bl = Wkl; bias = bk; Ch = Kh;  Cl = Kl;  }
    else             { Ah = Avh; Al = Avl; Bh = Wvh; Bl = Wvl; bias = bv; Ch = Vth; Cl = Vtl; }

    const int tid = threadIdx.x, wid = tid >> 5, lane = tid & 31;
    const int m0 = blockIdx.y * 128, n0 = blockIdx.x * 128;
    const int warpM = (wid >> 2) * 64, warpN = (wid & 3) * 32;

    float acc[4][4][4];
#pragma unroll
    for (int a = 0; a < 4; a++)
#pragma unroll
        for (int b = 0; b < 4; b++)
#pragma unroll
            for (int c = 0; c < 4; c++) acc[a][b][c] = 0.f;

    const int lrow = tid >> 1, qb = (tid & 1) * 4;
    const int nc = K >> 6;

    auto load_chunk = [&](int c, int b) {
        const uint32_t buf = tb + (uint32_t)b * 65536;
        const size_t aoff = (size_t)(m0 + lrow) * K + c * 64;
        const size_t boff = (size_t)(n0 + lrow) * K + c * 64;
#pragma unroll
        for (int j = 0; j < 4; j++) {
            const int q = qb + j;
            const uint32_t so = sw128((uint32_t)lrow * 128 + q * 16);
            cp16(buf + AH + so, Ah + aoff + q * 8);
            cp16(buf + AL + so, Al + aoff + q * 8);
            cp16(buf + BH + so, Bh + boff + q * 8);
            cp16(buf + BL + so, Bl + boff + q * 8);
        }
        asm volatile("cp.async.commit_group;" ::: "memory");
    };

    load_chunk(0, 0);
    for (int c = 0; c < nc; c++) {
        if (c + 1 < nc) {
            load_chunk(c + 1, (c + 1) & 1);
            asm volatile("cp.async.wait_group 1;" ::: "memory");
        } else {
            asm volatile("cp.async.wait_group 0;" ::: "memory");
        }
        __syncthreads();
        const uint32_t buf = tb + (uint32_t)(c & 1) * 65536;
        compute_chunk<4, 4>(buf + AH, buf + AL, buf + BH, buf + BL, warpM, warpN, lane, acc);
        __syncthreads();
    }

    const int r0 = lane >> 2, cj = (lane & 3) * 2;
#pragma unroll
    for (int mt = 0; mt < 4; mt++) {
#pragma unroll
        for (int nt = 0; nt < 4; nt++) {
            const int m = m0 + warpM + mt * 16 + r0;
            const int n = n0 + warpN + nt * 8 + cj;
            const float* cc = acc[mt][nt];
            float b0 = __ldg(bias + n), b1 = __ldg(bias + n + 1);
            float v0 = cc[0] + b0, v1 = cc[1] + b1, v2 = cc[2] + b0, v3 = cc[3] + b1;
            if (z < 2) {
                __nv_bfloat16 h0 = __float2bfloat16(v0), h1 = __float2bfloat16(v1);
                __nv_bfloat16 h2 = __float2bfloat16(v2), h3 = __float2bfloat16(v3);
                *(uint32_t*)(Ch + (size_t)m * N + n)       = bf2u(h0, h1);
                *(uint32_t*)(Ch + (size_t)(m + 8) * N + n) = bf2u(h2, h3);
                *(uint32_t*)(Cl + (size_t)m * N + n) =
                    packf_hi(v0 - __bfloat162float(h0), v1 - __bfloat162float(h1));
                *(uint32_t*)(Cl + (size_t)(m + 8) * N + n) =
                    packf_hi(v2 - __bfloat162float(h2), v3 - __bfloat162float(h3));
            } else {
                float v[4] = {v0, v1, v2, v3};
                int mm[4] = {m, m, m + 8, m + 8};
                int nn[4] = {n, n + 1, n, n + 1};
#pragma unroll
                for (int e = 0; e < 4; e++) {
                    __nv_bfloat16 hh = __float2bfloat16(v[e]);
                    Ch[(size_t)nn[e] * vt_stride + mm[e]] = hh;
                    Cl[(size_t)nn[e] * vt_stride + mm[e]] =
                        __float2bfloat16(v[e] - __bfloat162float(hh));
                }
            }
        }
    }
}

// ---------------------------------------------------------------------------
// FC GEMM (fp32 out)
// ---------------------------------------------------------------------------
__global__ __launch_bounds__(256)
void fc_hmma(const __nv_bfloat16* __restrict__ Ah, const __nv_bfloat16* __restrict__ Al,
             const __nv_bfloat16* __restrict__ Bh, const __nv_bfloat16* __restrict__ Bl,
             const float* __restrict__ bias, float* __restrict__ Cf, int N, int K)
{
    extern __shared__ char smem[];
    const uint32_t sb = smem_u32(smem);
    const uint32_t tb = (sb + 1023) & ~1023u;
    const uint32_t AH = 0, AL = 16384, BH = 32768, BL = 49152;

    const int tid = threadIdx.x, wid = tid >> 5, lane = tid & 31;
    const int m0 = blockIdx.y * 128, n0 = blockIdx.x * 128;
    const int warpM = (wid >> 2) * 64, warpN = (wid & 3) * 32;

    float acc[4][4][4];
#pragma unroll
    for (int a = 0; a < 4; a++)
#pragma unroll
        for (int b = 0; b < 4; b++)
#pragma unroll
            for (int c = 0; c < 4; c++) acc[a][b][c] = 0.f;

    const int lrow = tid >> 1, qb = (tid & 1) * 4;
    const int nc = K >> 6;

    auto load_chunk = [&](int c, int b) {
        const uint32_t buf = tb + (uint32_t)b * 65536;
        const size_t aoff = (size_t)(m0 + lrow) * K + c * 64;
        const size_t boff = (size_t)(n0 + lrow) * K + c * 64;
#pragma unroll
        for (int j = 0; j < 4; j++) {
            const int q = qb + j;
            const uint32_t so = sw128((uint32_t)lrow * 128 + q * 16);
            cp16(buf + AH + so, Ah + aoff + q * 8);
            cp16(buf + AL + so, Al + aoff + q * 8);
            cp16(buf + BH + so, Bh + boff + q * 8);
            cp16(buf + BL + so, Bl + boff + q * 8);
        }
        asm volatile("cp.async.commit_group;" ::: "memory");
    };

    load_chunk(0, 0);
    for (int c = 0; c < nc; c++) {
        if (c + 1 < nc) {
            load_chunk(c + 1, (c + 1) & 1);
            asm volatile("cp.async.wait_group 1;" ::: "memory");
        } else {
            asm volatile("cp.async.wait_group 0;" ::: "memory");
        }
        __syncthreads();
        const uint32_t buf = tb + (uint32_t)(c & 1) * 65536;
        compute_chunk<4, 4>(buf + AH, buf + AL, buf + BH, buf + BL, warpM, warpN, lane, acc);
        __syncthreads();
    }

    const int r0 = lane >> 2, cj = (lane & 3) * 2;
#pragma unroll
    for (int mt = 0; mt < 4; mt++) {
#pragma unroll
        for (int nt = 0; nt < 4; nt++) {
            const int m = m0 + warpM + mt * 16 + r0;
            const int n = n0 + warpN + nt * 8 + cj;
            const float* cc = acc[mt][nt];
            float b0 = __ldg(bias + n), b1 = __ldg(bias + n + 1);
            *(float2*)(Cf + (size_t)m * N + n)       = make_float2(cc[0] + b0, cc[1] + b1);
            *(float2*)(Cf + (size_t)(m + 8) * N + n) = make_float2(cc[2] + b0, cc[3] + b1);
        }
    }
}

// ---------------------------------------------------------------------------
// Scores: 4 n-tiles per block (BN strip = 512), Q tile reused, K tiles
// cp.async double-buffered. attn[h][m][n] = 0.125 * QK (raw).
// grid (S/512, L/128, H). smem: Q 32KB + 2x32KB K buffers.
// ---------------------------------------------------------------------------
#define SC_NT 4
__global__ __launch_bounds__(256)
void scores_hmma(const __nv_bfloat16* __restrict__ Qhp, const __nv_bfloat16* __restrict__ Qlp,
                 const __nv_bfloat16* __restrict__ Khp, const __nv_bfloat16* __restrict__ Klp,
                 float* __restrict__ attn, int L, int S)
{
    extern __shared__ char smem[];
    const uint32_t sb = smem_u32(smem);
    const uint32_t tb = (sb + 1023) & ~1023u;
    const uint32_t QH = 0, QL = 16384, KB = 32768;   // K buf b at KB + b*32768 (hi at +0, lo at +16384)

    const int tid = threadIdx.x, wid = tid >> 5, lane = tid & 31;
    const int n_base = blockIdx.x * (128 * SC_NT), m0 = blockIdx.y * 128, h = blockIdx.z;
    const int warpM = (wid >> 2) * 64, warpN = (wid & 3) * 32;

    const int lrow = tid >> 1, qb = (tid & 1) * 4;

    // Q tile (loads join K0's cp.async group)
    {
        const size_t qoff = (size_t)(m0 + lrow) * E_DIM + h * D_HEAD;
#pragma unroll
        for (int j = 0; j < 4; j++) {
            const int q = qb + j;
            const uint32_t so = sw128((uint32_t)lrow * 128 + q * 16);
            cp16(tb + QH + so, Qhp + qoff + q * 8);
            cp16(tb + QL + so, Qlp + qoff + q * 8);
        }
    }
    auto loadK = [&](int t, int b) {
        const uint32_t buf = tb + KB + (uint32_t)b * 32768;
        const size_t koff = (size_t)(n_base + t * 128 + lrow) * E_DIM + h * D_HEAD;
#pragma unroll
        for (int j = 0; j < 4; j++) {
            const int q = qb + j;
            const uint32_t so = sw128((uint32_t)lrow * 128 + q * 16);
            cp16(buf + so, Khp + koff + q * 8);
            cp16(buf + 16384 + so, Klp + koff + q * 8);
        }
        asm volatile("cp.async.commit_group;" ::: "memory");
    };

    loadK(0, 0);
    const int r0 = lane >> 2, cj = (lane & 3) * 2;
    for (int t = 0; t < SC_NT; t++) {
        if (t + 1 < SC_NT) {
            loadK(t + 1, (t + 1) & 1);
            asm volatile("cp.async.wait_group 1;" ::: "memory");
        } else {
            asm volatile("cp.async.wait_group 0;" ::: "memory");
        }
        __syncthreads();

        float acc[4][4][4];
#pragma unroll
        for (int a = 0; a < 4; a++)
#pragma unroll
            for (int b = 0; b < 4; b++)
#pragma unroll
                for (int c = 0; c < 4; c++) acc[a][b][c] = 0.f;

        const uint32_t kb = tb + KB + (uint32_t)(t & 1) * 32768;
        compute_chunk<4, 4>(tb + QH, tb + QL, kb, kb + 16384, warpM, warpN, lane, acc);

        const int n0 = n_base + t * 128;
#pragma unroll
        for (int mt = 0; mt < 4; mt++) {
#pragma unroll
            for (int nt = 0; nt < 4; nt++) {
                const int m = m0 + warpM + mt * 16 + r0;
                const int n = n0 + warpN + nt * 8 + cj;
                const float* cc = acc[mt][nt];
                *(float2*)(attn + ((size_t)h * L + m) * S + n) =
                    make_float2(cc[0] * 0.125f, cc[1] * 0.125f);
                *(float2*)(attn + ((size_t)h * L + m + 8) * S + n) =
                    make_float2(cc[2] * 0.125f, cc[3] * 0.125f);
            }
        }
        __syncthreads();
    }
}

// ---------------------------------------------------------------------------
// Row softmax, in-place, no max-shift, causal opt. (R10-proven.)
// ---------------------------------------------------------------------------
__global__ __launch_bounds__(256)
void softmax_kernel(float* __restrict__ attn, int L, int S,
                    const int* __restrict__ causal_flag)
{
    const int rowi = blockIdx.x;
    const int l = rowi % L;
    const bool causal = (*causal_flag) != 0;
    float* p = attn + (size_t)rowi * S;

    const int tid = threadIdx.x;
    const int per = S / (256 * 4);

    float v[16];
    float sum = 0.f;
    for (int i = 0; i < per; i++) {
        const int idx4 = tid + i * 256;
        float4 x = *(const float4*)(p + idx4 * 4);
        const int s0 = idx4 * 4;
        float* vv = v + i * 4;
        vv[0] = __expf(x.x); vv[1] = __expf(x.y);
        vv[2] = __expf(x.z); vv[3] = __expf(x.w);
        if (causal) {
#pragma unroll
            for (int j = 0; j < 4; j++)
                if (s0 + j > l) vv[j] = 0.f;
        }
        sum += vv[0] + vv[1] + vv[2] + vv[3];
    }

    __shared__ float red[8];
#pragma unroll
    for (int o = 16; o > 0; o >>= 1) sum += __shfl_xor_sync(0xffffffffu, sum, o);
    if ((tid & 31) == 0) red[tid >> 5] = sum;
    __syncthreads();
    float tot = red[0];
#pragma unroll
    for (int w = 1; w < 8; w++) tot += red[w];
    const float inv = 1.0f / tot;

    for (int i = 0; i < per; i++) {
        const int idx4 = tid + i * 256;
        float* vv = v + i * 4;
        *(float4*)(p + idx4 * 4) = make_float4(vv[0] * inv, vv[1] * inv, vv[2] * inv, vv[3] * inv);
    }
}

// ---------------------------------------------------------------------------
// PV: read-only attn (R10-proven). grid (L/128, H).
// ---------------------------------------------------------------------------
__global__ __launch_bounds__(256)
void pv_hmma(const float* __restrict__ attn,
             const __nv_bfloat16* __restrict__ Vth, const __nv_bfloat16* __restrict__ Vtl,
             __nv_bfloat16* __restrict__ Oh, __nv_bfloat16* __restrict__ Ol,
             int L, int S)
{
    extern __shared__ char smem[];
    const uint32_t sb = smem_u32(smem);
    const uint32_t tb = (sb + 1023) & ~1023u;
    char* tile = smem + (tb - sb);
    const uint32_t PH = 0, PL = 16384, VH = 32768, VL = 40960;

    const int tid = threadIdx.x, wid = tid >> 5, lane = tid & 31;
    const int m0 = blockIdx.x * 128, h = blockIdx.y;
    const int warpM = (wid >> 1) * 32, warpN = (wid & 1) * 32;

    float acc[2][4][4];
#pragma unroll
    for (int a = 0; a < 2; a++)
#pragma unroll
        for (int b = 0; b < 4; b++)
#pragma unroll
            for (int c = 0; c < 4; c++) acc[a][b][c] = 0.f;

    const int prow = tid >> 1, phalf = tid & 1;
    const int vrow = tid >> 2, vq = tid & 3;

    for (int c = 0; c < (S >> 6); c++) {
        const float4* psrc =
            (const float4*)(attn + ((size_t)h * L + m0 + prow) * S + c * 64 + phalf * 32);
#pragma unroll
        for (int j = 0; j < 8; j++) {
            float4 v = psrc[j];
            __nv_bfloat16 hx = __float2bfloat16(v.x), hy = __float2bfloat16(v.y);
            __nv_bfloat16 hz = __float2bfloat16(v.z), hw = __float2bfloat16(v.w);
            const uint32_t so = sw128((uint32_t)prow * 128 + phalf * 64 + j * 8);
            *(uint2*)(tile + PH + so) = make_uint2(bf2u(hx, hy), bf2u(hz, hw));
            *(uint2*)(tile + PL + so) = make_uint2(
                packf_hi(v.x - __bfloat162float(hx), v.y - __bfloat162float(hy)),
                packf_hi(v.z - __bfloat162float(hz), v.w - __bfloat162float(hw)));
        }
        const size_t vo = (size_t)(h * 64 + vrow) * S + c * 64;
#pragma unroll
        for (int jj = 0; jj < 2; jj++) {
            const int q = vq + jj * 4;
            const uint32_t so = sw128((uint32_t)vrow * 128 + q * 16);
            *(uint4*)(tile + VH + so) = *(const uint4*)(Vth + vo + q * 8);
            *(uint4*)(tile + VL + so) = *(const uint4*)(Vtl + vo + q * 8);
        }
        __syncthreads();
        compute_chunk<2, 4>(tb + PH, tb + PL, tb + VH, tb + VL, warpM, warpN, lane, acc);
        __syncthreads();
    }

    const int r0 = lane >> 2, cj = (lane & 3) * 2;
#pragma unroll
    for (int mt = 0; mt < 2; mt++) {
#pragma unroll
        for (int nt = 0; nt < 4; nt++) {
            const int m = m0 + warpM + mt * 16 + r0;
            const int n = h * 64 + warpN + nt * 8 + cj;
            const float* cc = acc[mt][nt];
            __nv_bfloat16 h0b = __float2bfloat16(cc[0]), h1b = __float2bfloat16(cc[1]);
            __nv_bfloat16 h2b = __float2bfloat16(cc[2]), h3b = __float2bfloat16(cc[3]);
            *(uint32_t*)(Oh + (size_t)m * E_DIM + n)       = bf2u(h0b, h1b);
            *(uint32_t*)(Oh + (size_t)(m + 8) * E_DIM + n) = bf2u(h2b, h3b);
            *(uint32_t*)(Ol + (size_t)m * E_DIM + n) =
                packf_hi(cc[0] - __bfloat162float(h0b), cc[1] - __bfloat162float(h1b));
            *(uint32_t*)(Ol + (size_t)(m + 8) * E_DIM + n) =
                packf_hi(cc[2] - __bfloat162float(h2b), cc[3] - __bfloat162float(h3b));
        }
    }
}

// ---------------------------------------------------------------------------
// Launch
// ---------------------------------------------------------------------------
extern "C" void kernel_launch(void* const* d_in, const int* in_sizes, int n_in,
                              void* d_out, int out_size)
{
    const float* query = (const float*)d_in[0];
    const float* key   = (const float*)d_in[1];
    const float* value = (const float*)d_in[2];
    const float* wq_w  = (const float*)d_in[3];
    const float* wq_b  = (const float*)d_in[4];
    const float* wk_w  = (const float*)d_in[5];
    const float* wk_b  = (const float*)d_in[6];
    const float* wv_w  = (const float*)d_in[7];
    const float* wv_b  = (const float*)d_in[8];
    const float* fc_w  = (const float*)d_in[9];
    const float* fc_b  = (const float*)d_in[10];
    const int* causal  = (const int*)d_in[11];

    const int L = in_sizes[0] / E_DIM;
    const int S = in_sizes[1] / E_DIM;

    float* out = (float*)d_out;
    float* attn_ptr;
    {
        size_t need = (size_t)L * E_DIM + (size_t)H_HEADS * L * S;
        if ((size_t)out_size >= need) attn_ptr = out + (size_t)L * E_DIM;
        else cudaGetSymbolAddress((void**)&attn_ptr, g_attn_fb);
    }

    __nv_bfloat16 *xqh, *xql, *xkh, *xkl, *xvh, *xvl;
    __nv_bfloat16 *wqh, *wql, *wkh, *wkl, *wvh, *wvl, *fch, *fcl;
    __nv_bfloat16 *qh, *ql, *kh, *kl, *vth, *vtl, *oh, *ol;
    cudaGetSymbolAddress((void**)&xqh, g_xq_h); cudaGetSymbolAddress((void**)&xql, g_xq_l);
    cudaGetSymbolAddress((void**)&xkh, g_xk_h); cudaGetSymbolAddress((void**)&xkl, g_xk_l);
    cudaGetSymbolAddress((void**)&xvh, g_xv_h); cudaGetSymbolAddress((void**)&xvl, g_xv_l);
    cudaGetSymbolAddress((void**)&wqh, g_wq_h); cudaGetSymbolAddress((void**)&wql, g_wq_l);
    cudaGetSymbolAddress((void**)&wkh, g_wk_h); cudaGetSymbolAddress((void**)&wkl, g_wk_l);
    cudaGetSymbolAddress((void**)&wvh, g_wv_h); cudaGetSymbolAddress((void**)&wvl, g_wv_l);
    cudaGetSymbolAddress((void**)&fch, g_fc_h); cudaGetSymbolAddress((void**)&fcl, g_fc_l);
    cudaGetSymbolAddress((void**)&qh, g_q_h);   cudaGetSymbolAddress((void**)&ql, g_q_l);
    cudaGetSymbolAddress((void**)&kh, g_k_h);   cudaGetSymbolAddress((void**)&kl, g_k_l);
    cudaGetSymbolAddress((void**)&vth, g_vt_h); cudaGetSymbolAddress((void**)&vtl, g_vt_l);
    cudaGetSymbolAddress((void**)&oh, g_o_h);   cudaGetSymbolAddress((void**)&ol, g_o_l);

    const int GEMM_SMEM   = 1024 + 2 * 65536;
    const int SCORES_SMEM = 1024 + 32768 + 2 * 32768;   // Q + 2 K buffers = 99328
    const int PV_SMEM     = 1024 + 49152;
    cudaFuncSetAttribute(qkv_hmma,    cudaFuncAttributeMaxDynamicSharedMemorySize, GEMM_SMEM);
    cudaFuncSetAttribute(fc_hmma,     cudaFuncAttributeMaxDynamicSharedMemorySize, GEMM_SMEM);
    cudaFuncSetAttribute(scores_hmma, cudaFuncAttributeMaxDynamicSharedMemorySize, SCORES_SMEM);
    cudaFuncSetAttribute(pv_hmma,     cudaFuncAttributeMaxDynamicSharedMemorySize, PV_SMEM);

    // launch 0: all hi/lo conversions fused
    {
        const int na4 = (L * E_DIM) / 4, nw4 = (E_DIM * E_DIM) / 4;
        cvt_all<<<1024, 256>>>(query, key, value, wq_w, wk_w, wv_w, fc_w,
                               xqh, xql, xkh, xkl, xvh, xvl,
                               wqh, wql, wkh, wkl, wvh, wvl, fch, fcl,
                               na4, nw4);
    }

    // launch 1: Q/K/V projections merged
    {
        dim3 grid(E_DIM / 128, L / 128, 3);
        qkv_hmma<<<grid, 256, GEMM_SMEM>>>(
            xqh, xql, xkh, xkl, xvh, xvl,
            wqh, wql, wkh, wkl, wvh, wvl,
            wq_b, wk_b, wv_b,
            qh, ql, kh, kl, vth, vtl,
            E_DIM, E_DIM, S);
    }

    // launch 2: scores (raw, scaled), 4 n-tiles per block, pipelined
    {
        dim3 grid(S / (128 * SC_NT), L / 128, H_HEADS);
        scores_hmma<<<grid, 256, SCORES_SMEM>>>(qh, ql, kh, kl, attn_ptr, L, S);
    }

    // launch 3: softmax
    softmax_kernel<<<H_HEADS * L, 256>>>(attn_ptr, L, S, causal);

    // launch 4: PV
    {
        dim3 grid(L / 128, H_HEADS);
        pv_hmma<<<grid, 256, PV_SMEM>>>(attn_ptr, vth, vtl, oh, ol, L, S);
    }

    // launch 5: FC
    {
        dim3 grid(E_DIM / 128, L / 128);
        fc_hmma<<<grid, 256, GEMM_SMEM>>>(oh, ol, fch, fcl, fc_b, out, E_DIM, E_DIM);
    }
}

// round 14
// speedup vs baseline: 1.1757x; 1.0329x over previous
#include <cuda_runtime.h>
#include <cuda_bf16.h>
#include <stdint.h>
#include <math.h>

#define E_DIM 1024
#define H_HEADS 16
#define D_HEAD 64
#define L_MAX 4096

// ---------------------------------------------------------------------------
// Device scratch (allocation-free kernel_launch)
// ---------------------------------------------------------------------------
__device__ __nv_bfloat16 g_xq_h[L_MAX * E_DIM], g_xq_l[L_MAX * E_DIM];
__device__ __nv_bfloat16 g_xk_h[L_MAX * E_DIM], g_xk_l[L_MAX * E_DIM];
__device__ __nv_bfloat16 g_xv_h[L_MAX * E_DIM], g_xv_l[L_MAX * E_DIM];
__device__ __nv_bfloat16 g_wq_h[E_DIM * E_DIM], g_wq_l[E_DIM * E_DIM];
__device__ __nv_bfloat16 g_wk_h[E_DIM * E_DIM], g_wk_l[E_DIM * E_DIM];
__device__ __nv_bfloat16 g_wv_h[E_DIM * E_DIM], g_wv_l[E_DIM * E_DIM];
__device__ __nv_bfloat16 g_fc_h[E_DIM * E_DIM], g_fc_l[E_DIM * E_DIM];
__device__ __nv_bfloat16 g_q_h[L_MAX * E_DIM], g_q_l[L_MAX * E_DIM];
__device__ __nv_bfloat16 g_k_h[L_MAX * E_DIM], g_k_l[L_MAX * E_DIM];
__device__ __nv_bfloat16 g_vt_h[E_DIM * L_MAX], g_vt_l[E_DIM * L_MAX];   // [E][S]
__device__ __nv_bfloat16 g_o_h[L_MAX * E_DIM], g_o_l[L_MAX * E_DIM];
__device__ float g_attn_fb[(size_t)H_HEADS * L_MAX * L_MAX];

#define DINLINE __device__ __forceinline__

DINLINE uint32_t smem_u32(const void* p) {
    uint32_t a;
    asm("{ .reg .u64 t; cvta.to.shared.u64 t, %1; cvt.u32.u64 %0, t; }" : "=r"(a) : "l"(p));
    return a;
}
DINLINE uint32_t sw128(uint32_t off) { return off ^ ((off >> 3) & 0x70); }

DINLINE void ldsm_x4(uint32_t& r0, uint32_t& r1, uint32_t& r2, uint32_t& r3, uint32_t addr) {
    asm volatile("ldmatrix.sync.aligned.m8n8.x4.shared.b16 {%0,%1,%2,%3}, [%4];"
                 : "=r"(r0), "=r"(r1), "=r"(r2), "=r"(r3) : "r"(addr));
}
DINLINE void ldsm_x2(uint32_t& r0, uint32_t& r1, uint32_t addr) {
    asm volatile("ldmatrix.sync.aligned.m8n8.x2.shared.b16 {%0,%1}, [%2];"
                 : "=r"(r0), "=r"(r1) : "r"(addr));
}
DINLINE void mma16816(float c[4], uint32_t a0, uint32_t a1, uint32_t a2, uint32_t a3,
                      uint32_t b0, uint32_t b1) {
    asm volatile(
        "mma.sync.aligned.m16n8k16.row.col.f32.bf16.bf16.f32 "
        "{%0,%1,%2,%3}, {%4,%5,%6,%7}, {%8,%9}, {%0,%1,%2,%3};"
        : "+f"(c[0]), "+f"(c[1]), "+f"(c[2]), "+f"(c[3])
        : "r"(a0), "r"(a1), "r"(a2), "r"(a3), "r"(b0), "r"(b1));
}
DINLINE void cp16(uint32_t dst, const void* src) {
    asm volatile("cp.async.ca.shared.global [%0], [%1], 16;" :: "r"(dst), "l"(src));
}

DINLINE uint32_t bf2u(__nv_bfloat16 a, __nv_bfloat16 b) {
    __nv_bfloat162 t = __halves2bfloat162(a, b);
    return *reinterpret_cast<uint32_t*>(&t);
}
DINLINE uint32_t packf_hi(float a, float b) {
    return bf2u(__float2bfloat16(a), __float2bfloat16(b));
}

// ---------------------------------------------------------------------------
// Core: one KC=64 chunk, bf16x3 emulated fp32 (hi*hi + hi*lo + lo*hi).
// ---------------------------------------------------------------------------
template<int MT, int NT>
DINLINE void compute_chunk(uint32_t aHi, uint32_t aLo, uint32_t bHi, uint32_t bLo,
                           int warpM, int warpN, int lane, float (&acc)[MT][NT][4])
{
    const int arow = lane & 15, asel = lane >> 4;
    const int brow = lane & 7,  bsel = (lane >> 3) & 1;
#pragma unroll
    for (int ks = 0; ks < 4; ks++) {
        uint32_t bh[NT][2], bl[NT][2];
        uint32_t ah[MT][4], al[MT][4];
        const uint32_t bcol = (uint32_t)(ks * 16 + bsel * 8) * 2;
#pragma unroll
        for (int nt = 0; nt < NT; nt++) {
            uint32_t off = sw128((uint32_t)(warpN + nt * 8 + brow) * 128 + bcol);
            ldsm_x2(bh[nt][0], bh[nt][1], bHi + off);
            ldsm_x2(bl[nt][0], bl[nt][1], bLo + off);
        }
        const uint32_t acol = (uint32_t)(ks * 16 + asel * 8) * 2;
#pragma unroll
        for (int mt = 0; mt < MT; mt++) {
            uint32_t off = sw128((uint32_t)(warpM + mt * 16 + arow) * 128 + acol);
            ldsm_x4(ah[mt][0], ah[mt][1], ah[mt][2], ah[mt][3], aHi + off);
            ldsm_x4(al[mt][0], al[mt][1], al[mt][2], al[mt][3], aLo + off);
        }
#pragma unroll
        for (int mt = 0; mt < MT; mt++)
#pragma unroll
            for (int nt = 0; nt < NT; nt++)
                mma16816(acc[mt][nt], ah[mt][0], ah[mt][1], ah[mt][2], ah[mt][3],
                         bh[nt][0], bh[nt][1]);
#pragma unroll
        for (int mt = 0; mt < MT; mt++)
#pragma unroll
            for (int nt = 0; nt < NT; nt++)
                mma16816(acc[mt][nt], ah[mt][0], ah[mt][1], ah[mt][2], ah[mt][3],
                         bl[nt][0], bl[nt][1]);
#pragma unroll
        for (int mt = 0; mt < MT; mt++)
#pragma unroll
            for (int nt = 0; nt < NT; nt++)
                mma16816(acc[mt][nt], al[mt][0], al[mt][1], al[mt][2], al[mt][3],
                         bh[nt][0], bh[nt][1]);
    }
}

// ---------------------------------------------------------------------------
// Fused fp32 -> bf16 hi/lo split for all 7 tensors (one launch)
// ---------------------------------------------------------------------------
__global__ void cvt_all(const float* __restrict__ s0, const float* __restrict__ s1,
                        const float* __restrict__ s2, const float* __restrict__ s3,
                        const float* __restrict__ s4, const float* __restrict__ s5,
                        const float* __restrict__ s6,
                        __nv_bfloat16* __restrict__ h0, __nv_bfloat16* __restrict__ l0,
                        __nv_bfloat16* __restrict__ h1, __nv_bfloat16* __restrict__ l1,
                        __nv_bfloat16* __restrict__ h2, __nv_bfloat16* __restrict__ l2,
                        __nv_bfloat16* __restrict__ h3, __nv_bfloat16* __restrict__ l3,
                        __nv_bfloat16* __restrict__ h4, __nv_bfloat16* __restrict__ l4,
                        __nv_bfloat16* __restrict__ h5, __nv_bfloat16* __restrict__ l5,
                        __nv_bfloat16* __restrict__ h6, __nv_bfloat16* __restrict__ l6,
                        int na4, int nw4)
{
    const int total = 3 * na4 + 4 * nw4;
    for (int i = blockIdx.x * blockDim.x + threadIdx.x; i < total;
         i += gridDim.x * blockDim.x) {
        const float* src; __nv_bfloat16* hh; __nv_bfloat16* ll; int j;
        if (i < na4)          { src = s0; hh = h0; ll = l0; j = i; }
        else if (i < 2 * na4) { src = s1; hh = h1; ll = l1; j = i - na4; }
        else if (i < 3 * na4) { src = s2; hh = h2; ll = l2; j = i - 2 * na4; }
        else {
            int k = i - 3 * na4;
            if (k < nw4)          { src = s3; hh = h3; ll = l3; j = k; }
            else if (k < 2 * nw4) { src = s4; hh = h4; ll = l4; j = k - nw4; }
            else if (k < 3 * nw4) { src = s5; hh = h5; ll = l5; j = k - 2 * nw4; }
            else                  { src = s6; hh = h6; ll = l6; j = k - 3 * nw4; }
        }
        float4 v = ((const float4*)src)[j];
        __nv_bfloat16 hx = __float2bfloat16(v.x), hy = __float2bfloat16(v.y);
        __nv_bfloat16 hz = __float2bfloat16(v.z), hw = __float2bfloat16(v.w);
        ((uint2*)hh)[j] = make_uint2(bf2u(hx, hy), bf2u(hz, hw));
        ((uint2*)ll)[j] = make_uint2(
            packf_hi(v.x - __bfloat162float(hx), v.y - __bfloat162float(hy)),
            packf_hi(v.z - __bfloat162float(hz), v.w - __bfloat162float(hw)));
    }
}

// ---------------------------------------------------------------------------
// Merged Q/K/V projection GEMM: grid.z selects weight set / output.
// ---------------------------------------------------------------------------
__global__ __launch_bounds__(256)
void qkv_hmma(const __nv_bfloat16* __restrict__ Aqh, const __nv_bfloat16* __restrict__ Aql,
              const __nv_bfloat16* __restrict__ Akh, const __nv_bfloat16* __restrict__ Akl,
              const __nv_bfloat16* __restrict__ Avh, const __nv_bfloat16* __restrict__ Avl,
              const __nv_bfloat16* __restrict__ Wqh, const __nv_bfloat16* __restrict__ Wql,
              const __nv_bfloat16* __restrict__ Wkh, const __nv_bfloat16* __restrict__ Wkl,
              const __nv_bfloat16* __restrict__ Wvh, const __nv_bfloat16* __restrict__ Wvl,
              const float* __restrict__ bq, const float* __restrict__ bk,
              const float* __restrict__ bv,
              __nv_bfloat16* __restrict__ Qh, __nv_bfloat16* __restrict__ Ql,
              __nv_bfloat16* __restrict__ Kh, __nv_bfloat16* __restrict__ Kl,
              __nv_bfloat16* __restrict__ Vth, __nv_bfloat16* __restrict__ Vtl,
              int N, int K, int vt_stride)
{
    extern __shared__ char smem[];
    const uint32_t sb = smem_u32(smem);
    const uint32_t tb = (sb + 1023) & ~1023u;
    const uint32_t AH = 0, AL = 16384, BH = 32768, BL = 49152;

    const int z = blockIdx.z;
    const __nv_bfloat16 *Ah, *Al, *Bh, *Bl;
    const float* bias;
    __nv_bfloat16 *Ch, *Cl;
    if (z == 0)      { Ah = Aqh; Al = Aql; Bh = Wqh; Bl = Wql; bias = bq; Ch = Qh;  Cl = Ql;  }
    else if (z == 1) { Ah = Akh; Al = Akl; Bh = Wkh; Bl = Wkl; bias = bk; Ch = Kh;  Cl = Kl;  }
    else             { Ah = Avh; Al = Avl; Bh = Wvh; Bl = Wvl; bias = bv; Ch = Vth; Cl = Vtl; }

    const int tid = threadIdx.x, wid = tid >> 5, lane = tid & 31;
    const int m0 = blockIdx.y * 128, n0 = blockIdx.x * 128;
    const int warpM = (wid >> 2) * 64, warpN = (wid & 3) * 32;

    float acc[4][4][4];
#pragma unroll
    for (int a = 0; a < 4; a++)
#pragma unroll
        for (int b = 0; b < 4; b++)
#pragma unroll
            for (int c = 0; c < 4; c++) acc[a][b][c] = 0.f;

    const int lrow = tid >> 1, qb = (tid & 1) * 4;
    const int nc = K >> 6;

    auto load_chunk = [&](int c, int b) {
        const uint32_t buf = tb + (uint32_t)b * 65536;
        const size_t aoff = (size_t)(m0 + lrow) * K + c * 64;
        const size_t boff = (size_t)(n0 + lrow) * K + c * 64;
#pragma unroll
        for (int j = 0; j < 4; j++) {
            const int q = qb + j;
            const uint32_t so = sw128((uint32_t)lrow * 128 + q * 16);
            cp16(buf + AH + so, Ah + aoff + q * 8);
            cp16(buf + AL + so, Al + aoff + q * 8);
            cp16(buf + BH + so, Bh + boff + q * 8);
            cp16(buf + BL + so, Bl + boff + q * 8);
        }
        asm volatile("cp.async.commit_group;" ::: "memory");
    };

    load_chunk(0, 0);
    for (int c = 0; c < nc; c++) {
        if (c + 1 < nc) {
            load_chunk(c + 1, (c + 1) & 1);
            asm volatile("cp.async.wait_group 1;" ::: "memory");
        } else {
            asm volatile("cp.async.wait_group 0;" ::: "memory");
        }
        __syncthreads();
        const uint32_t buf = tb + (uint32_t)(c & 1) * 65536;
        compute_chunk<4, 4>(buf + AH, buf + AL, buf + BH, buf + BL, warpM, warpN, lane, acc);
        __syncthreads();
    }

    const int r0 = lane >> 2, cj = (lane & 3) * 2;
#pragma unroll
    for (int mt = 0; mt < 4; mt++) {
#pragma unroll
        for (int nt = 0; nt < 4; nt++) {
            const int m = m0 + warpM + mt * 16 + r0;
            const int n = n0 + warpN + nt * 8 + cj;
            const float* cc = acc[mt][nt];
            float b0 = __ldg(bias + n), b1 = __ldg(bias + n + 1);
            float v0 = cc[0] + b0, v1 = cc[1] + b1, v2 = cc[2] + b0, v3 = cc[3] + b1;
            if (z < 2) {
                __nv_bfloat16 h0 = __float2bfloat16(v0), h1 = __float2bfloat16(v1);
                __nv_bfloat16 h2 = __float2bfloat16(v2), h3 = __float2bfloat16(v3);
                *(uint32_t*)(Ch + (size_t)m * N + n)       = bf2u(h0, h1);
                *(uint32_t*)(Ch + (size_t)(m + 8) * N + n) = bf2u(h2, h3);
                *(uint32_t*)(Cl + (size_t)m * N + n) =
                    packf_hi(v0 - __bfloat162float(h0), v1 - __bfloat162float(h1));
                *(uint32_t*)(Cl + (size_t)(m + 8) * N + n) =
                    packf_hi(v2 - __bfloat162float(h2), v3 - __bfloat162float(h3));
            } else {
                float v[4] = {v0, v1, v2, v3};
                int mm[4] = {m, m, m + 8, m + 8};
                int nn[4] = {n, n + 1, n, n + 1};
#pragma unroll
                for (int e = 0; e < 4; e++) {
                    __nv_bfloat16 hh = __float2bfloat16(v[e]);
                    Ch[(size_t)nn[e] * vt_stride + mm[e]] = hh;
                    Cl[(size_t)nn[e] * vt_stride + mm[e]] =
                        __float2bfloat16(v[e] - __bfloat162float(hh));
                }
            }
        }
    }
}

// ---------------------------------------------------------------------------
// FC GEMM (fp32 out)
// ---------------------------------------------------------------------------
__global__ __launch_bounds__(256)
void fc_hmma(const __nv_bfloat16* __restrict__ Ah, const __nv_bfloat16* __restrict__ Al,
             const __nv_bfloat16* __restrict__ Bh, const __nv_bfloat16* __restrict__ Bl,
             const float* __restrict__ bias, float* __restrict__ Cf, int N, int K)
{
    extern __shared__ char smem[];
    const uint32_t sb = smem_u32(smem);
    const uint32_t tb = (sb + 1023) & ~1023u;
    const uint32_t AH = 0, AL = 16384, BH = 32768, BL = 49152;

    const int tid = threadIdx.x, wid = tid >> 5, lane = tid & 31;
    const int m0 = blockIdx.y * 128, n0 = blockIdx.x * 128;
    const int warpM = (wid >> 2) * 64, warpN = (wid & 3) * 32;

    float acc[4][4][4];
#pragma unroll
    for (int a = 0; a < 4; a++)
#pragma unroll
        for (int b = 0; b < 4; b++)
#pragma unroll
            for (int c = 0; c < 4; c++) acc[a][b][c] = 0.f;

    const int lrow = tid >> 1, qb = (tid & 1) * 4;
    const int nc = K >> 6;

    auto load_chunk = [&](int c, int b) {
        const uint32_t buf = tb + (uint32_t)b * 65536;
        const size_t aoff = (size_t)(m0 + lrow) * K + c * 64;
        const size_t boff = (size_t)(n0 + lrow) * K + c * 64;
#pragma unroll
        for (int j = 0; j < 4; j++) {
            const int q = qb + j;
            const uint32_t so = sw128((uint32_t)lrow * 128 + q * 16);
            cp16(buf + AH + so, Ah + aoff + q * 8);
            cp16(buf + AL + so, Al + aoff + q * 8);
            cp16(buf + BH + so, Bh + boff + q * 8);
            cp16(buf + BL + so, Bl + boff + q * 8);
        }
        asm volatile("cp.async.commit_group;" ::: "memory");
    };

    load_chunk(0, 0);
    for (int c = 0; c < nc; c++) {
        if (c + 1 < nc) {
            load_chunk(c + 1, (c + 1) & 1);
            asm volatile("cp.async.wait_group 1;" ::: "memory");
        } else {
            asm volatile("cp.async.wait_group 0;" ::: "memory");
        }
        __syncthreads();
        const uint32_t buf = tb + (uint32_t)(c & 1) * 65536;
        compute_chunk<4, 4>(buf + AH, buf + AL, buf + BH, buf + BL, warpM, warpN, lane, acc);
        __syncthreads();
    }

    const int r0 = lane >> 2, cj = (lane & 3) * 2;
#pragma unroll
    for (int mt = 0; mt < 4; mt++) {
#pragma unroll
        for (int nt = 0; nt < 4; nt++) {
            const int m = m0 + warpM + mt * 16 + r0;
            const int n = n0 + warpN + nt * 8 + cj;
            const float* cc = acc[mt][nt];
            float b0 = __ldg(bias + n), b1 = __ldg(bias + n + 1);
            *(float2*)(Cf + (size_t)m * N + n)       = make_float2(cc[0] + b0, cc[1] + b1);
            *(float2*)(Cf + (size_t)(m + 8) * N + n) = make_float2(cc[2] + b0, cc[3] + b1);
        }
    }
}

// ---------------------------------------------------------------------------
// Scores: 4 n-tiles per block, Q reused, K double-buffered (R13-proven).
// Streaming stores (attn is a 1GB one-shot stream).
// grid (S/512, L/128, H).
// ---------------------------------------------------------------------------
#define SC_NT 4
__global__ __launch_bounds__(256)
void scores_hmma(const __nv_bfloat16* __restrict__ Qhp, const __nv_bfloat16* __restrict__ Qlp,
                 const __nv_bfloat16* __restrict__ Khp, const __nv_bfloat16* __restrict__ Klp,
                 float* __restrict__ attn, int L, int S)
{
    extern __shared__ char smem[];
    const uint32_t sb = smem_u32(smem);
    const uint32_t tb = (sb + 1023) & ~1023u;
    const uint32_t QH = 0, QL = 16384, KB = 32768;

    const int tid = threadIdx.x, wid = tid >> 5, lane = tid & 31;
    const int n_base = blockIdx.x * (128 * SC_NT), m0 = blockIdx.y * 128, h = blockIdx.z;
    const int warpM = (wid >> 2) * 64, warpN = (wid & 3) * 32;

    const int lrow = tid >> 1, qb = (tid & 1) * 4;

    {
        const size_t qoff = (size_t)(m0 + lrow) * E_DIM + h * D_HEAD;
#pragma unroll
        for (int j = 0; j < 4; j++) {
            const int q = qb + j;
            const uint32_t so = sw128((uint32_t)lrow * 128 + q * 16);
            cp16(tb + QH + so, Qhp + qoff + q * 8);
            cp16(tb + QL + so, Qlp + qoff + q * 8);
        }
    }
    auto loadK = [&](int t, int b) {
        const uint32_t buf = tb + KB + (uint32_t)b * 32768;
        const size_t koff = (size_t)(n_base + t * 128 + lrow) * E_DIM + h * D_HEAD;
#pragma unroll
        for (int j = 0; j < 4; j++) {
            const int q = qb + j;
            const uint32_t so = sw128((uint32_t)lrow * 128 + q * 16);
            cp16(buf + so, Khp + koff + q * 8);
            cp16(buf + 16384 + so, Klp + koff + q * 8);
        }
        asm volatile("cp.async.commit_group;" ::: "memory");
    };

    loadK(0, 0);
    const int r0 = lane >> 2, cj = (lane & 3) * 2;
    for (int t = 0; t < SC_NT; t++) {
        if (t + 1 < SC_NT) {
            loadK(t + 1, (t + 1) & 1);
            asm volatile("cp.async.wait_group 1;" ::: "memory");
        } else {
            asm volatile("cp.async.wait_group 0;" ::: "memory");
        }
        __syncthreads();

        float acc[4][4][4];
#pragma unroll
        for (int a = 0; a < 4; a++)
#pragma unroll
            for (int b = 0; b < 4; b++)
#pragma unroll
                for (int c = 0; c < 4; c++) acc[a][b][c] = 0.f;

        const uint32_t kb = tb + KB + (uint32_t)(t & 1) * 32768;
        compute_chunk<4, 4>(tb + QH, tb + QL, kb, kb + 16384, warpM, warpN, lane, acc);

        const int n0 = n_base + t * 128;
#pragma unroll
        for (int mt = 0; mt < 4; mt++) {
#pragma unroll
            for (int nt = 0; nt < 4; nt++) {
                const int m = m0 + warpM + mt * 16 + r0;
                const int n = n0 + warpN + nt * 8 + cj;
                const float* cc = acc[mt][nt];
                __stcs((float2*)(attn + ((size_t)h * L + m) * S + n),
                       make_float2(cc[0] * 0.125f, cc[1] * 0.125f));
                __stcs((float2*)(attn + ((size_t)h * L + m + 8) * S + n),
                       make_float2(cc[2] * 0.125f, cc[3] * 0.125f));
            }
        }
        __syncthreads();
    }
}

// ---------------------------------------------------------------------------
// Row softmax, in-place, no max-shift, streaming loads/stores.
// ---------------------------------------------------------------------------
__global__ __launch_bounds__(256)
void softmax_kernel(float* __restrict__ attn, int L, int S,
                    const int* __restrict__ causal_flag)
{
    const int rowi = blockIdx.x;
    const int l = rowi % L;
    const bool causal = (*causal_flag) != 0;
    float* p = attn + (size_t)rowi * S;

    const int tid = threadIdx.x;
    const int per = S / (256 * 4);

    float v[16];
    float sum = 0.f;
    for (int i = 0; i < per; i++) {
        const int idx4 = tid + i * 256;
        float4 x = __ldcs((const float4*)(p + idx4 * 4));
        const int s0 = idx4 * 4;
        float* vv = v + i * 4;
        vv[0] = __expf(x.x); vv[1] = __expf(x.y);
        vv[2] = __expf(x.z); vv[3] = __expf(x.w);
        if (causal) {
#pragma unroll
            for (int j = 0; j < 4; j++)
                if (s0 + j > l) vv[j] = 0.f;
        }
        sum += vv[0] + vv[1] + vv[2] + vv[3];
    }

    __shared__ float red[8];
#pragma unroll
    for (int o = 16; o > 0; o >>= 1) sum += __shfl_xor_sync(0xffffffffu, sum, o);
    if ((tid & 31) == 0) red[tid >> 5] = sum;
    __syncthreads();
    float tot = red[0];
#pragma unroll
    for (int w = 1; w < 8; w++) tot += red[w];
    const float inv = 1.0f / tot;

    for (int i = 0; i < per; i++) {
        const int idx4 = tid + i * 256;
        float* vv = v + i * 4;
        __stcs((float4*)(p + idx4 * 4),
               make_float4(vv[0] * inv, vv[1] * inv, vv[2] * inv, vv[3] * inv));
    }
}

// ---------------------------------------------------------------------------
// PV, pipelined: V via cp.async double-buffered; P(c+1) prefetched into regs
// (streaming loads) during compute of chunk c, converted+STS'd after.
// grid (L/128, H). Stage stride 48KB x2.
// ---------------------------------------------------------------------------
__global__ __launch_bounds__(256)
void pv_hmma(const float* __restrict__ attn,
             const __nv_bfloat16* __restrict__ Vth, const __nv_bfloat16* __restrict__ Vtl,
             __nv_bfloat16* __restrict__ Oh, __nv_bfloat16* __restrict__ Ol,
             int L, int S)
{
    extern __shared__ char smem[];
    const uint32_t sb = smem_u32(smem);
    const uint32_t tb = (sb + 1023) & ~1023u;
    const uint32_t ST = 49152;                       // stage stride
    const uint32_t PH = 0, PL = 16384, VH = 32768, VL = 40960;

    const int tid = threadIdx.x, wid = tid >> 5, lane = tid & 31;
    const int m0 = blockIdx.x * 128, h = blockIdx.y;
    const int warpM = (wid >> 1) * 32, warpN = (wid & 1) * 32;

    const int prow = tid >> 1, phalf = tid & 1;
    const int vrow = tid >> 2, vq = tid & 3;
    const float* rowbase = attn + ((size_t)h * L + m0 + prow) * S + phalf * 32;

    auto loadV = [&](int c) {
        const uint32_t buf = tb + (uint32_t)(c & 1) * ST;
        const size_t vo = (size_t)(h * 64 + vrow) * S + c * 64;
#pragma unroll
        for (int jj = 0; jj < 2; jj++) {
            const int q = vq + jj * 4;
            const uint32_t so = sw128((uint32_t)vrow * 128 + q * 16);
            cp16(buf + VH + so, Vth + vo + q * 8);
            cp16(buf + VL + so, Vtl + vo + q * 8);
        }
        asm volatile("cp.async.commit_group;" ::: "memory");
    };
    auto stsP = [&](int c, const float4* pr) {
        const uint32_t buf = tb + (uint32_t)(c & 1) * ST;
#pragma unroll
        for (int j = 0; j < 8; j++) {
            float4 v = pr[j];
            __nv_bfloat16 hx = __float2bfloat16(v.x), hy = __float2bfloat16(v.y);
            __nv_bfloat16 hz = __float2bfloat16(v.z), hw = __float2bfloat16(v.w);
            const uint32_t so = sw128((uint32_t)prow * 128 + phalf * 64 + j * 8);
            *(uint2*)(smem + (buf - sb) + PH + so) = make_uint2(bf2u(hx, hy), bf2u(hz, hw));
            *(uint2*)(smem + (buf - sb) + PL + so) = make_uint2(
                packf_hi(v.x - __bfloat162float(hx), v.y - __bfloat162float(hy)),
                packf_hi(v.z - __bfloat162float(hz), v.w - __bfloat162float(hw)));
        }
    };

    float acc[2][4][4];
#pragma unroll
    for (int a = 0; a < 2; a++)
#pragma unroll
        for (int b = 0; b < 4; b++)
#pragma unroll
            for (int c = 0; c < 4; c++) acc[a][b][c] = 0.f;

    const int nc = S >> 6;
    float4 pbuf[8];

    // prologue: P(0) -> smem stage 0, V(0) async
    {
        const float4* ps = (const float4*)(rowbase);
#pragma unroll
        for (int j = 0; j < 8; j++) pbuf[j] = __ldcs(ps + j);
        loadV(0);
        stsP(0, pbuf);
    }

    for (int c = 0; c < nc; c++) {
        if (c + 1 < nc) {
            const float4* ps = (const float4*)(rowbase + (c + 1) * 64);
#pragma unroll
            for (int j = 0; j < 8; j++) pbuf[j] = __ldcs(ps + j);   // prefetch P(c+1)
            loadV(c + 1);
            asm volatile("cp.async.wait_group 1;" ::: "memory");
        } else {
            asm volatile("cp.async.wait_group 0;" ::: "memory");
        }
        __syncthreads();   // stage c fully ready (P STS from prev iter + V arrival)
        const uint32_t buf = tb + (uint32_t)(c & 1) * ST;
        compute_chunk<2, 4>(buf + PH, buf + PL, buf + VH, buf + VL, warpM, warpN, lane, acc);
        __syncthreads();   // stage (c+1)&1 free for writing
        if (c + 1 < nc) stsP(c + 1, pbuf);
    }

    const int r0 = lane >> 2, cj = (lane & 3) * 2;
#pragma unroll
    for (int mt = 0; mt < 2; mt++) {
#pragma unroll
        for (int nt = 0; nt < 4; nt++) {
            const int m = m0 + warpM + mt * 16 + r0;
            const int n = h * 64 + warpN + nt * 8 + cj;
            const float* cc = acc[mt][nt];
            __nv_bfloat16 h0b = __float2bfloat16(cc[0]), h1b = __float2bfloat16(cc[1]);
            __nv_bfloat16 h2b = __float2bfloat16(cc[2]), h3b = __float2bfloat16(cc[3]);
            *(uint32_t*)(Oh + (size_t)m * E_DIM + n)       = bf2u(h0b, h1b);
            *(uint32_t*)(Oh + (size_t)(m + 8) * E_DIM + n) = bf2u(h2b, h3b);
            *(uint32_t*)(Ol + (size_t)m * E_DIM + n) =
                packf_hi(cc[0] - __bfloat162float(h0b), cc[1] - __bfloat162float(h1b));
            *(uint32_t*)(Ol + (size_t)(m + 8) * E_DIM + n) =
                packf_hi(cc[2] - __bfloat162float(h2b), cc[3] - __bfloat162float(h3b));
        }
    }
}

// ---------------------------------------------------------------------------
// Launch
// ---------------------------------------------------------------------------
extern "C" void kernel_launch(void* const* d_in, const int* in_sizes, int n_in,
                              void* d_out, int out_size)
{
    const float* query = (const float*)d_in[0];
    const float* key   = (const float*)d_in[1];
    const float* value = (const float*)d_in[2];
    const float* wq_w  = (const float*)d_in[3];
    const float* wq_b  = (const float*)d_in[4];
    const float* wk_w  = (const float*)d_in[5];
    const float* wk_b  = (const float*)d_in[6];
    const float* wv_w  = (const float*)d_in[7];
    const float* wv_b  = (const float*)d_in[8];
    const float* fc_w  = (const float*)d_in[9];
    const float* fc_b  = (const float*)d_in[10];
    const int* causal  = (const int*)d_in[11];

    const int L = in_sizes[0] / E_DIM;
    const int S = in_sizes[1] / E_DIM;

    float* out = (float*)d_out;
    float* attn_ptr;
    {
        size_t need = (size_t)L * E_DIM + (size_t)H_HEADS * L * S;
        if ((size_t)out_size >= need) attn_ptr = out + (size_t)L * E_DIM;
        else cudaGetSymbolAddress((void**)&attn_ptr, g_attn_fb);
    }

    __nv_bfloat16 *xqh, *xql, *xkh, *xkl, *xvh, *xvl;
    __nv_bfloat16 *wqh, *wql, *wkh, *wkl, *wvh, *wvl, *fch, *fcl;
    __nv_bfloat16 *qh, *ql, *kh, *kl, *vth, *vtl, *oh, *ol;
    cudaGetSymbolAddress((void**)&xqh, g_xq_h); cudaGetSymbolAddress((void**)&xql, g_xq_l);
    cudaGetSymbolAddress((void**)&xkh, g_xk_h); cudaGetSymbolAddress((void**)&xkl, g_xk_l);
    cudaGetSymbolAddress((void**)&xvh, g_xv_h); cudaGetSymbolAddress((void**)&xvl, g_xv_l);
    cudaGetSymbolAddress((void**)&wqh, g_wq_h); cudaGetSymbolAddress((void**)&wql, g_wq_l);
    cudaGetSymbolAddress((void**)&wkh, g_wk_h); cudaGetSymbolAddress((void**)&wkl, g_wk_l);
    cudaGetSymbolAddress((void**)&wvh, g_wv_h); cudaGetSymbolAddress((void**)&wvl, g_wv_l);
    cudaGetSymbolAddress((void**)&fch, g_fc_h); cudaGetSymbolAddress((void**)&fcl, g_fc_l);
    cudaGetSymbolAddress((void**)&qh, g_q_h);   cudaGetSymbolAddress((void**)&ql, g_q_l);
    cudaGetSymbolAddress((void**)&kh, g_k_h);   cudaGetSymbolAddress((void**)&kl, g_k_l);
    cudaGetSymbolAddress((void**)&vth, g_vt_h); cudaGetSymbolAddress((void**)&vtl, g_vt_l);
    cudaGetSymbolAddress((void**)&oh, g_o_h);   cudaGetSymbolAddress((void**)&ol, g_o_l);

    const int GEMM_SMEM   = 1024 + 2 * 65536;
    const int SCORES_SMEM = 1024 + 32768 + 2 * 32768;
    const int PV_SMEM     = 1024 + 2 * 49152;   // two 48KB stages
    cudaFuncSetAttribute(qkv_hmma,    cudaFuncAttributeMaxDynamicSharedMemorySize, GEMM_SMEM);
    cudaFuncSetAttribute(fc_hmma,     cudaFuncAttributeMaxDynamicSharedMemorySize, GEMM_SMEM);
    cudaFuncSetAttribute(scores_hmma, cudaFuncAttributeMaxDynamicSharedMemorySize, SCORES_SMEM);
    cudaFuncSetAttribute(pv_hmma,     cudaFuncAttributeMaxDynamicSharedMemorySize, PV_SMEM);

    // launch 0: all hi/lo conversions fused
    {
        const int na4 = (L * E_DIM) / 4, nw4 = (E_DIM * E_DIM) / 4;
        cvt_all<<<1024, 256>>>(query, key, value, wq_w, wk_w, wv_w, fc_w,
                               xqh, xql, xkh, xkl, xvh, xvl,
                               wqh, wql, wkh, wkl, wvh, wvl, fch, fcl,
                               na4, nw4);
    }

    // launch 1: Q/K/V projections merged
    {
        dim3 grid(E_DIM / 128, L / 128, 3);
        qkv_hmma<<<grid, 256, GEMM_SMEM>>>(
            xqh, xql, xkh, xkl, xvh, xvl,
            wqh, wql, wkh, wkl, wvh, wvl,
            wq_b, wk_b, wv_b,
            qh, ql, kh, kl, vth, vtl,
            E_DIM, E_DIM, S);
    }

    // launch 2: scores
    {
        dim3 grid(S / (128 * SC_NT), L / 128, H_HEADS);
        scores_hmma<<<grid, 256, SCORES_SMEM>>>(qh, ql, kh, kl, attn_ptr, L, S);
    }

    // launch 3: softmax
    softmax_kernel<<<H_HEADS * L, 256>>>(attn_ptr, L, S, causal);

    // launch 4: PV (pipelined)
    {
        dim3 grid(L / 128, H_HEADS);
        pv_hmma<<<grid, 256, PV_SMEM>>>(attn_ptr, vth, vtl, oh, ol, L, S);
    }

    // launch 5: FC
    {
        dim3 grid(E_DIM / 128, L / 128);
        fc_hmma<<<grid, 256, GEMM_SMEM>>>(oh, ol, fch, fcl, fc_b, out, E_DIM, E_DIM);
    }
}

// round 15
// speedup vs baseline: 1.2240x; 1.0410x over previous
#include <cuda_runtime.h>
#include <cuda_bf16.h>
#include <stdint.h>
#include <math.h>

#define E_DIM 1024
#define H_HEADS 16
#define D_HEAD 64
#define L_MAX 4096

// ---------------------------------------------------------------------------
// Device scratch (allocation-free kernel_launch)
// ---------------------------------------------------------------------------
__device__ __nv_bfloat16 g_xq_h[L_MAX * E_DIM], g_xq_l[L_MAX * E_DIM];
__device__ __nv_bfloat16 g_xk_h[L_MAX * E_DIM], g_xk_l[L_MAX * E_DIM];
__device__ __nv_bfloat16 g_xv_h[L_MAX * E_DIM], g_xv_l[L_MAX * E_DIM];
__device__ __nv_bfloat16 g_wq_h[E_DIM * E_DIM], g_wq_l[E_DIM * E_DIM];
__device__ __nv_bfloat16 g_wk_h[E_DIM * E_DIM], g_wk_l[E_DIM * E_DIM];
__device__ __nv_bfloat16 g_wv_h[E_DIM * E_DIM], g_wv_l[E_DIM * E_DIM];
__device__ __nv_bfloat16 g_fc_h[E_DIM * E_DIM], g_fc_l[E_DIM * E_DIM];
__device__ __nv_bfloat16 g_q_h[L_MAX * E_DIM], g_q_l[L_MAX * E_DIM];
__device__ __nv_bfloat16 g_k_h[L_MAX * E_DIM], g_k_l[L_MAX * E_DIM];
__device__ __nv_bfloat16 g_vt_h[E_DIM * L_MAX], g_vt_l[E_DIM * L_MAX];   // [E][S]
__device__ __nv_bfloat16 g_o_h[L_MAX * E_DIM], g_o_l[L_MAX * E_DIM];
__device__ float g_attn_fb[(size_t)H_HEADS * L_MAX * L_MAX];

#define DINLINE __device__ __forceinline__

DINLINE uint32_t smem_u32(const void* p) {
    uint32_t a;
    asm("{ .reg .u64 t; cvta.to.shared.u64 t, %1; cvt.u32.u64 %0, t; }" : "=r"(a) : "l"(p));
    return a;
}
DINLINE uint32_t sw128(uint32_t off) { return off ^ ((off >> 3) & 0x70); }

DINLINE void ldsm_x4(uint32_t& r0, uint32_t& r1, uint32_t& r2, uint32_t& r3, uint32_t addr) {
    asm volatile("ldmatrix.sync.aligned.m8n8.x4.shared.b16 {%0,%1,%2,%3}, [%4];"
                 : "=r"(r0), "=r"(r1), "=r"(r2), "=r"(r3) : "r"(addr));
}
DINLINE void ldsm_x2(uint32_t& r0, uint32_t& r1, uint32_t addr) {
    asm volatile("ldmatrix.sync.aligned.m8n8.x2.shared.b16 {%0,%1}, [%2];"
                 : "=r"(r0), "=r"(r1) : "r"(addr));
}
DINLINE void mma16816(float c[4], uint32_t a0, uint32_t a1, uint32_t a2, uint32_t a3,
                      uint32_t b0, uint32_t b1) {
    asm volatile(
        "mma.sync.aligned.m16n8k16.row.col.f32.bf16.bf16.f32 "
        "{%0,%1,%2,%3}, {%4,%5,%6,%7}, {%8,%9}, {%0,%1,%2,%3};"
        : "+f"(c[0]), "+f"(c[1]), "+f"(c[2]), "+f"(c[3])
        : "r"(a0), "r"(a1), "r"(a2), "r"(a3), "r"(b0), "r"(b1));
}
DINLINE void cp16(uint32_t dst, const void* src) {
    asm volatile("cp.async.ca.shared.global [%0], [%1], 16;" :: "r"(dst), "l"(src));
}

DINLINE uint32_t bf2u(__nv_bfloat16 a, __nv_bfloat16 b) {
    __nv_bfloat162 t = __halves2bfloat162(a, b);
    return *reinterpret_cast<uint32_t*>(&t);
}
DINLINE uint32_t packf_hi(float a, float b) {
    return bf2u(__float2bfloat16(a), __float2bfloat16(b));
}

// ---------------------------------------------------------------------------
// Core: one KC=64 chunk, bf16x3 emulated fp32 (hi*hi + hi*lo + lo*hi).
// ---------------------------------------------------------------------------
template<int MT, int NT>
DINLINE void compute_chunk(uint32_t aHi, uint32_t aLo, uint32_t bHi, uint32_t bLo,
                           int warpM, int warpN, int lane, float (&acc)[MT][NT][4])
{
    const int arow = lane & 15, asel = lane >> 4;
    const int brow = lane & 7,  bsel = (lane >> 3) & 1;
#pragma unroll
    for (int ks = 0; ks < 4; ks++) {
        uint32_t bh[NT][2], bl[NT][2];
        uint32_t ah[MT][4], al[MT][4];
        const uint32_t bcol = (uint32_t)(ks * 16 + bsel * 8) * 2;
#pragma unroll
        for (int nt = 0; nt < NT; nt++) {
            uint32_t off = sw128((uint32_t)(warpN + nt * 8 + brow) * 128 + bcol);
            ldsm_x2(bh[nt][0], bh[nt][1], bHi + off);
            ldsm_x2(bl[nt][0], bl[nt][1], bLo + off);
        }
        const uint32_t acol = (uint32_t)(ks * 16 + asel * 8) * 2;
#pragma unroll
        for (int mt = 0; mt < MT; mt++) {
            uint32_t off = sw128((uint32_t)(warpM + mt * 16 + arow) * 128 + acol);
            ldsm_x4(ah[mt][0], ah[mt][1], ah[mt][2], ah[mt][3], aHi + off);
            ldsm_x4(al[mt][0], al[mt][1], al[mt][2], al[mt][3], aLo + off);
        }
#pragma unroll
        for (int mt = 0; mt < MT; mt++)
#pragma unroll
            for (int nt = 0; nt < NT; nt++)
                mma16816(acc[mt][nt], ah[mt][0], ah[mt][1], ah[mt][2], ah[mt][3],
                         bh[nt][0], bh[nt][1]);
#pragma unroll
        for (int mt = 0; mt < MT; mt++)
#pragma unroll
            for (int nt = 0; nt < NT; nt++)
                mma16816(acc[mt][nt], ah[mt][0], ah[mt][1], ah[mt][2], ah[mt][3],
                         bl[nt][0], bl[nt][1]);
#pragma unroll
        for (int mt = 0; mt < MT; mt++)
#pragma unroll
            for (int nt = 0; nt < NT; nt++)
                mma16816(acc[mt][nt], al[mt][0], al[mt][1], al[mt][2], al[mt][3],
                         bh[nt][0], bh[nt][1]);
    }
}

// ---------------------------------------------------------------------------
// Fused fp32 -> bf16 hi/lo split for all 7 tensors (one launch)
// ---------------------------------------------------------------------------
__global__ void cvt_all(const float* __restrict__ s0, const float* __restrict__ s1,
                        const float* __restrict__ s2, const float* __restrict__ s3,
                        const float* __restrict__ s4, const float* __restrict__ s5,
                        const float* __restrict__ s6,
                        __nv_bfloat16* __restrict__ h0, __nv_bfloat16* __restrict__ l0,
                        __nv_bfloat16* __restrict__ h1, __nv_bfloat16* __restrict__ l1,
                        __nv_bfloat16* __restrict__ h2, __nv_bfloat16* __restrict__ l2,
                        __nv_bfloat16* __restrict__ h3, __nv_bfloat16* __restrict__ l3,
                        __nv_bfloat16* __restrict__ h4, __nv_bfloat16* __restrict__ l4,
                        __nv_bfloat16* __restrict__ h5, __nv_bfloat16* __restrict__ l5,
                        __nv_bfloat16* __restrict__ h6, __nv_bfloat16* __restrict__ l6,
                        int na4, int nw4)
{
    const int total = 3 * na4 + 4 * nw4;
    for (int i = blockIdx.x * blockDim.x + threadIdx.x; i < total;
         i += gridDim.x * blockDim.x) {
        const float* src; __nv_bfloat16* hh; __nv_bfloat16* ll; int j;
        if (i < na4)          { src = s0; hh = h0; ll = l0; j = i; }
        else if (i < 2 * na4) { src = s1; hh = h1; ll = l1; j = i - na4; }
        else if (i < 3 * na4) { src = s2; hh = h2; ll = l2; j = i - 2 * na4; }
        else {
            int k = i - 3 * na4;
            if (k < nw4)          { src = s3; hh = h3; ll = l3; j = k; }
            else if (k < 2 * nw4) { src = s4; hh = h4; ll = l4; j = k - nw4; }
            else if (k < 3 * nw4) { src = s5; hh = h5; ll = l5; j = k - 2 * nw4; }
            else                  { src = s6; hh = h6; ll = l6; j = k - 3 * nw4; }
        }
        float4 v = ((const float4*)src)[j];
        __nv_bfloat16 hx = __float2bfloat16(v.x), hy = __float2bfloat16(v.y);
        __nv_bfloat16 hz = __float2bfloat16(v.z), hw = __float2bfloat16(v.w);
        ((uint2*)hh)[j] = make_uint2(bf2u(hx, hy), bf2u(hz, hw));
        ((uint2*)ll)[j] = make_uint2(
            packf_hi(v.x - __bfloat162float(hx), v.y - __bfloat162float(hy)),
            packf_hi(v.z - __bfloat162float(hz), v.w - __bfloat162float(hw)));
    }
}

// ---------------------------------------------------------------------------
// Merged Q/K/V projection GEMM: 512 threads, 16 warps (4x4 grid of 32x32
// warp tiles), cp.async double-buffered. grid.z selects weight set / output.
// ---------------------------------------------------------------------------
__global__ __launch_bounds__(512)
void qkv_hmma(const __nv_bfloat16* __restrict__ Aqh, const __nv_bfloat16* __restrict__ Aql,
              const __nv_bfloat16* __restrict__ Akh, const __nv_bfloat16* __restrict__ Akl,
              const __nv_bfloat16* __restrict__ Avh, const __nv_bfloat16* __restrict__ Avl,
              const __nv_bfloat16* __restrict__ Wqh, const __nv_bfloat16* __restrict__ Wql,
              const __nv_bfloat16* __restrict__ Wkh, const __nv_bfloat16* __restrict__ Wkl,
              const __nv_bfloat16* __restrict__ Wvh, const __nv_bfloat16* __restrict__ Wvl,
              const float* __restrict__ bq, const float* __restrict__ bk,
              const float* __restrict__ bv,
              __nv_bfloat16* __restrict__ Qh, __nv_bfloat16* __restrict__ Ql,
              __nv_bfloat16* __restrict__ Kh, __nv_bfloat16* __restrict__ Kl,
              __nv_bfloat16* __restrict__ Vth, __nv_bfloat16* __restrict__ Vtl,
              int N, int K, int vt_stride)
{
    extern __shared__ char smem[];
    const uint32_t sb = smem_u32(smem);
    const uint32_t tb = (sb + 1023) & ~1023u;
    const uint32_t AH = 0, AL = 16384, BH = 32768, BL = 49152;

    const int z = blockIdx.z;
    const __nv_bfloat16 *Ah, *Al, *Bh, *Bl;
    const float* bias;
    __nv_bfloat16 *Ch, *Cl;
    if (z == 0)      { Ah = Aqh; Al = Aql; Bh = Wqh; Bl = Wql; bias = bq; Ch = Qh;  Cl = Ql;  }
    else if (z == 1) { Ah = Akh; Al = Akl; Bh = Wkh; Bl = Wkl; bias = bk; Ch = Kh;  Cl = Kl;  }
    else             { Ah = Avh; Al = Avl; Bh = Wvh; Bl = Wvl; bias = bv; Ch = Vth; Cl = Vtl; }

    const int tid = threadIdx.x, wid = tid >> 5, lane = tid & 31;
    const int m0 = blockIdx.y * 128, n0 = blockIdx.x * 128;
    const int warpM = (wid >> 2) * 32, warpN = (wid & 3) * 32;

    float acc[2][4][4];
#pragma unroll
    for (int a = 0; a < 2; a++)
#pragma unroll
        for (int b = 0; b < 4; b++)
#pragma unroll
            for (int c = 0; c < 4; c++) acc[a][b][c] = 0.f;

    const int lrow = tid >> 2, qb = (tid & 3) * 2;
    const int nc = K >> 6;

    auto load_chunk = [&](int c, int b) {
        const uint32_t buf = tb + (uint32_t)b * 65536;
        const size_t aoff = (size_t)(m0 + lrow) * K + c * 64;
        const size_t boff = (size_t)(n0 + lrow) * K + c * 64;
#pragma unroll
        for (int j = 0; j < 2; j++) {
            const int q = qb + j;
            const uint32_t so = sw128((uint32_t)lrow * 128 + q * 16);
            cp16(buf + AH + so, Ah + aoff + q * 8);
            cp16(buf + AL + so, Al + aoff + q * 8);
            cp16(buf + BH + so, Bh + boff + q * 8);
            cp16(buf + BL + so, Bl + boff + q * 8);
        }
        asm volatile("cp.async.commit_group;" ::: "memory");
    };

    load_chunk(0, 0);
    for (int c = 0; c < nc; c++) {
        if (c + 1 < nc) {
            load_chunk(c + 1, (c + 1) & 1);
            asm volatile("cp.async.wait_group 1;" ::: "memory");
        } else {
            asm volatile("cp.async.wait_group 0;" ::: "memory");
        }
        __syncthreads();
        const uint32_t buf = tb + (uint32_t)(c & 1) * 65536;
        compute_chunk<2, 4>(buf + AH, buf + AL, buf + BH, buf + BL, warpM, warpN, lane, acc);
        __syncthreads();
    }

    const int r0 = lane >> 2, cj = (lane & 3) * 2;
#pragma unroll
    for (int mt = 0; mt < 2; mt++) {
#pragma unroll
        for (int nt = 0; nt < 4; nt++) {
            const int m = m0 + warpM + mt * 16 + r0;
            const int n = n0 + warpN + nt * 8 + cj;
            const float* cc = acc[mt][nt];
            float b0 = __ldg(bias + n), b1 = __ldg(bias + n + 1);
            float v0 = cc[0] + b0, v1 = cc[1] + b1, v2 = cc[2] + b0, v3 = cc[3] + b1;
            if (z < 2) {
                __nv_bfloat16 h0 = __float2bfloat16(v0), h1 = __float2bfloat16(v1);
                __nv_bfloat16 h2 = __float2bfloat16(v2), h3 = __float2bfloat16(v3);
                *(uint32_t*)(Ch + (size_t)m * N + n)       = bf2u(h0, h1);
                *(uint32_t*)(Ch + (size_t)(m + 8) * N + n) = bf2u(h2, h3);
                *(uint32_t*)(Cl + (size_t)m * N + n) =
                    packf_hi(v0 - __bfloat162float(h0), v1 - __bfloat162float(h1));
                *(uint32_t*)(Cl + (size_t)(m + 8) * N + n) =
                    packf_hi(v2 - __bfloat162float(h2), v3 - __bfloat162float(h3));
            } else {
                float v[4] = {v0, v1, v2, v3};
                int mm[4] = {m, m, m + 8, m + 8};
                int nn[4] = {n, n + 1, n, n + 1};
#pragma unroll
                for (int e = 0; e < 4; e++) {
                    __nv_bfloat16 hh = __float2bfloat16(v[e]);
                    Ch[(size_t)nn[e] * vt_stride + mm[e]] = hh;
                    Cl[(size_t)nn[e] * vt_stride + mm[e]] =
                        __float2bfloat16(v[e] - __bfloat162float(hh));
                }
            }
        }
    }
}

// ---------------------------------------------------------------------------
// FC GEMM (fp32 out), 512 threads, 16 warps.
// ---------------------------------------------------------------------------
__global__ __launch_bounds__(512)
void fc_hmma(const __nv_bfloat16* __restrict__ Ah, const __nv_bfloat16* __restrict__ Al,
             const __nv_bfloat16* __restrict__ Bh, const __nv_bfloat16* __restrict__ Bl,
             const float* __restrict__ bias, float* __restrict__ Cf, int N, int K)
{
    extern __shared__ char smem[];
    const uint32_t sb = smem_u32(smem);
    const uint32_t tb = (sb + 1023) & ~1023u;
    const uint32_t AH = 0, AL = 16384, BH = 32768, BL = 49152;

    const int tid = threadIdx.x, wid = tid >> 5, lane = tid & 31;
    const int m0 = blockIdx.y * 128, n0 = blockIdx.x * 128;
    const int warpM = (wid >> 2) * 32, warpN = (wid & 3) * 32;

    float acc[2][4][4];
#pragma unroll
    for (int a = 0; a < 2; a++)
#pragma unroll
        for (int b = 0; b < 4; b++)
#pragma unroll
            for (int c = 0; c < 4; c++) acc[a][b][c] = 0.f;

    const int lrow = tid >> 2, qb = (tid & 3) * 2;
    const int nc = K >> 6;

    auto load_chunk = [&](int c, int b) {
        const uint32_t buf = tb + (uint32_t)b * 65536;
        const size_t aoff = (size_t)(m0 + lrow) * K + c * 64;
        const size_t boff = (size_t)(n0 + lrow) * K + c * 64;
#pragma unroll
        for (int j = 0; j < 2; j++) {
            const int q = qb + j;
            const uint32_t so = sw128((uint32_t)lrow * 128 + q * 16);
            cp16(buf + AH + so, Ah + aoff + q * 8);
            cp16(buf + AL + so, Al + aoff + q * 8);
            cp16(buf + BH + so, Bh + boff + q * 8);
            cp16(buf + BL + so, Bl + boff + q * 8);
        }
        asm volatile("cp.async.commit_group;" ::: "memory");
    };

    load_chunk(0, 0);
    for (int c = 0; c < nc; c++) {
        if (c + 1 < nc) {
            load_chunk(c + 1, (c + 1) & 1);
            asm volatile("cp.async.wait_group 1;" ::: "memory");
        } else {
            asm volatile("cp.async.wait_group 0;" ::: "memory");
        }
        __syncthreads();
        const uint32_t buf = tb + (uint32_t)(c & 1) * 65536;
        compute_chunk<2, 4>(buf + AH, buf + AL, buf + BH, buf + BL, warpM, warpN, lane, acc);
        __syncthreads();
    }

    const int r0 = lane >> 2, cj = (lane & 3) * 2;
#pragma unroll
    for (int mt = 0; mt < 2; mt++) {
#pragma unroll
        for (int nt = 0; nt < 4; nt++) {
            const int m = m0 + warpM + mt * 16 + r0;
            const int n = n0 + warpN + nt * 8 + cj;
            const float* cc = acc[mt][nt];
            float b0 = __ldg(bias + n), b1 = __ldg(bias + n + 1);
            *(float2*)(Cf + (size_t)m * N + n)       = make_float2(cc[0] + b0, cc[1] + b1);
            *(float2*)(Cf + (size_t)(m + 8) * N + n) = make_float2(cc[2] + b0, cc[3] + b1);
        }
    }
}

// ---------------------------------------------------------------------------
// Scores: 512 threads, 16 warps; 4 n-tiles per block, Q reused, K
// double-buffered; streaming stores. grid (S/512, L/128, H).
// ---------------------------------------------------------------------------
#define SC_NT 4
__global__ __launch_bounds__(512)
void scores_hmma(const __nv_bfloat16* __restrict__ Qhp, const __nv_bfloat16* __restrict__ Qlp,
                 const __nv_bfloat16* __restrict__ Khp, const __nv_bfloat16* __restrict__ Klp,
                 float* __restrict__ attn, int L, int S)
{
    extern __shared__ char smem[];
    const uint32_t sb = smem_u32(smem);
    const uint32_t tb = (sb + 1023) & ~1023u;
    const uint32_t QH = 0, QL = 16384, KB = 32768;

    const int tid = threadIdx.x, wid = tid >> 5, lane = tid & 31;
    const int n_base = blockIdx.x * (128 * SC_NT), m0 = blockIdx.y * 128, h = blockIdx.z;
    const int warpM = (wid >> 2) * 32, warpN = (wid & 3) * 32;

    const int lrow = tid >> 2, qb = (tid & 3) * 2;

    {
        const size_t qoff = (size_t)(m0 + lrow) * E_DIM + h * D_HEAD;
#pragma unroll
        for (int j = 0; j < 2; j++) {
            const int q = qb + j;
            const uint32_t so = sw128((uint32_t)lrow * 128 + q * 16);
            cp16(tb + QH + so, Qhp + qoff + q * 8);
            cp16(tb + QL + so, Qlp + qoff + q * 8);
        }
    }
    auto loadK = [&](int t, int b) {
        const uint32_t buf = tb + KB + (uint32_t)b * 32768;
        const size_t koff = (size_t)(n_base + t * 128 + lrow) * E_DIM + h * D_HEAD;
#pragma unroll
        for (int j = 0; j < 2; j++) {
            const int q = qb + j;
            const uint32_t so = sw128((uint32_t)lrow * 128 + q * 16);
            cp16(buf + so, Khp + koff + q * 8);
            cp16(buf + 16384 + so, Klp + koff + q * 8);
        }
        asm volatile("cp.async.commit_group;" ::: "memory");
    };

    loadK(0, 0);
    const int r0 = lane >> 2, cj = (lane & 3) * 2;
    for (int t = 0; t < SC_NT; t++) {
        if (t + 1 < SC_NT) {
            loadK(t + 1, (t + 1) & 1);
            asm volatile("cp.async.wait_group 1;" ::: "memory");
        } else {
            asm volatile("cp.async.wait_group 0;" ::: "memory");
        }
        __syncthreads();

        float acc[2][4][4];
#pragma unroll
        for (int a = 0; a < 2; a++)
#pragma unroll
            for (int b = 0; b < 4; b++)
#pragma unroll
                for (int c = 0; c < 4; c++) acc[a][b][c] = 0.f;

        const uint32_t kb = tb + KB + (uint32_t)(t & 1) * 32768;
        compute_chunk<2, 4>(tb + QH, tb + QL, kb, kb + 16384, warpM, warpN, lane, acc);

        const int n0 = n_base + t * 128;
#pragma unroll
        for (int mt = 0; mt < 2; mt++) {
#pragma unroll
            for (int nt = 0; nt < 4; nt++) {
                const int m = m0 + warpM + mt * 16 + r0;
                const int n = n0 + warpN + nt * 8 + cj;
                const float* cc = acc[mt][nt];
                __stcs((float2*)(attn + ((size_t)h * L + m) * S + n),
                       make_float2(cc[0] * 0.125f, cc[1] * 0.125f));
                __stcs((float2*)(attn + ((size_t)h * L + m + 8) * S + n),
                       make_float2(cc[2] * 0.125f, cc[3] * 0.125f));
            }
        }
        __syncthreads();
    }
}

// ---------------------------------------------------------------------------
// Row softmax, in-place, no max-shift, streaming loads/stores. (R14-proven.)
// ---------------------------------------------------------------------------
__global__ __launch_bounds__(256)
void softmax_kernel(float* __restrict__ attn, int L, int S,
                    const int* __restrict__ causal_flag)
{
    const int rowi = blockIdx.x;
    const int l = rowi % L;
    const bool causal = (*causal_flag) != 0;
    float* p = attn + (size_t)rowi * S;

    const int tid = threadIdx.x;
    const int per = S / (256 * 4);

    float v[16];
    float sum = 0.f;
    for (int i = 0; i < per; i++) {
        const int idx4 = tid + i * 256;
        float4 x = __ldcs((const float4*)(p + idx4 * 4));
        const int s0 = idx4 * 4;
        float* vv = v + i * 4;
        vv[0] = __expf(x.x); vv[1] = __expf(x.y);
        vv[2] = __expf(x.z); vv[3] = __expf(x.w);
        if (causal) {
#pragma unroll
            for (int j = 0; j < 4; j++)
                if (s0 + j > l) vv[j] = 0.f;
        }
        sum += vv[0] + vv[1] + vv[2] + vv[3];
    }

    __shared__ float red[8];
#pragma unroll
    for (int o = 16; o > 0; o >>= 1) sum += __shfl_xor_sync(0xffffffffu, sum, o);
    if ((tid & 31) == 0) red[tid >> 5] = sum;
    __syncthreads();
    float tot = red[0];
#pragma unroll
    for (int w = 1; w < 8; w++) tot += red[w];
    const float inv = 1.0f / tot;

    for (int i = 0; i < per; i++) {
        const int idx4 = tid + i * 256;
        float* vv = v + i * 4;
        __stcs((float4*)(p + idx4 * 4),
               make_float4(vv[0] * inv, vv[1] * inv, vv[2] * inv, vv[3] * inv));
    }
}

// ---------------------------------------------------------------------------
// PV, pipelined (R14-proven): V via cp.async; P(c+1) prefetched into regs
// during compute of chunk c. grid (L/128, H). 256 threads.
// ---------------------------------------------------------------------------
__global__ __launch_bounds__(256)
void pv_hmma(const float* __restrict__ attn,
             const __nv_bfloat16* __restrict__ Vth, const __nv_bfloat16* __restrict__ Vtl,
             __nv_bfloat16* __restrict__ Oh, __nv_bfloat16* __restrict__ Ol,
             int L, int S)
{
    extern __shared__ char smem[];
    const uint32_t sb = smem_u32(smem);
    const uint32_t tb = (sb + 1023) & ~1023u;
    const uint32_t ST = 49152;
    const uint32_t PH = 0, PL = 16384, VH = 32768, VL = 40960;

    const int tid = threadIdx.x, wid = tid >> 5, lane = tid & 31;
    const int m0 = blockIdx.x * 128, h = blockIdx.y;
    const int warpM = (wid >> 1) * 32, warpN = (wid & 1) * 32;

    const int prow = tid >> 1, phalf = tid & 1;
    const int vrow = tid >> 2, vq = tid & 3;
    const float* rowbase = attn + ((size_t)h * L + m0 + prow) * S + phalf * 32;

    auto loadV = [&](int c) {
        const uint32_t buf = tb + (uint32_t)(c & 1) * ST;
        const size_t vo = (size_t)(h * 64 + vrow) * S + c * 64;
#pragma unroll
        for (int jj = 0; jj < 2; jj++) {
            const int q = vq + jj * 4;
            const uint32_t so = sw128((uint32_t)vrow * 128 + q * 16);
            cp16(buf + VH + so, Vth + vo + q * 8);
            cp16(buf + VL + so, Vtl + vo + q * 8);
        }
        asm volatile("cp.async.commit_group;" ::: "memory");
    };
    auto stsP = [&](int c, const float4* pr) {
        const uint32_t buf = tb + (uint32_t)(c & 1) * ST;
#pragma unroll
        for (int j = 0; j < 8; j++) {
            float4 v = pr[j];
            __nv_bfloat16 hx = __float2bfloat16(v.x), hy = __float2bfloat16(v.y);
            __nv_bfloat16 hz = __float2bfloat16(v.z), hw = __float2bfloat16(v.w);
            const uint32_t so = sw128((uint32_t)prow * 128 + phalf * 64 + j * 8);
            *(uint2*)(smem + (buf - sb) + PH + so) = make_uint2(bf2u(hx, hy), bf2u(hz, hw));
            *(uint2*)(smem + (buf - sb) + PL + so) = make_uint2(
                packf_hi(v.x - __bfloat162float(hx), v.y - __bfloat162float(hy)),
                packf_hi(v.z - __bfloat162float(hz), v.w - __bfloat162float(hw)));
        }
    };

    float acc[2][4][4];
#pragma unroll
    for (int a = 0; a < 2; a++)
#pragma unroll
        for (int b = 0; b < 4; b++)
#pragma unroll
            for (int c = 0; c < 4; c++) acc[a][b][c] = 0.f;

    const int nc = S >> 6;
    float4 pbuf[8];

    {
        const float4* ps = (const float4*)(rowbase);
#pragma unroll
        for (int j = 0; j < 8; j++) pbuf[j] = __ldcs(ps + j);
        loadV(0);
        stsP(0, pbuf);
    }

    for (int c = 0; c < nc; c++) {
        if (c + 1 < nc) {
            const float4* ps = (const float4*)(rowbase + (c + 1) * 64);
#pragma unroll
            for (int j = 0; j < 8; j++) pbuf[j] = __ldcs(ps + j);
            loadV(c + 1);
            asm volatile("cp.async.wait_group 1;" ::: "memory");
        } else {
            asm volatile("cp.async.wait_group 0;" ::: "memory");
        }
        __syncthreads();
        const uint32_t buf = tb + (uint32_t)(c & 1) * ST;
        compute_chunk<2, 4>(buf + PH, buf + PL, buf + VH, buf + VL, warpM, warpN, lane, acc);
        __syncthreads();
        if (c + 1 < nc) stsP(c + 1, pbuf);
    }

    const int r0 = lane >> 2, cj = (lane & 3) * 2;
#pragma unroll
    for (int mt = 0; mt < 2; mt++) {
#pragma unroll
        for (int nt = 0; nt < 4; nt++) {
            const int m = m0 + warpM + mt * 16 + r0;
            const int n = h * 64 + warpN + nt * 8 + cj;
            const float* cc = acc[mt][nt];
            __nv_bfloat16 h0b = __float2bfloat16(cc[0]), h1b = __float2bfloat16(cc[1]);
            __nv_bfloat16 h2b = __float2bfloat16(cc[2]), h3b = __float2bfloat16(cc[3]);
            *(uint32_t*)(Oh + (size_t)m * E_DIM + n)       = bf2u(h0b, h1b);
            *(uint32_t*)(Oh + (size_t)(m + 8) * E_DIM + n) = bf2u(h2b, h3b);
            *(uint32_t*)(Ol + (size_t)m * E_DIM + n) =
                packf_hi(cc[0] - __bfloat162float(h0b), cc[1] - __bfloat162float(h1b));
            *(uint32_t*)(Ol + (size_t)(m + 8) * E_DIM + n) =
                packf_hi(cc[2] - __bfloat162float(h2b), cc[3] - __bfloat162float(h3b));
        }
    }
}

// ---------------------------------------------------------------------------
// Launch
// ---------------------------------------------------------------------------
extern "C" void kernel_launch(void* const* d_in, const int* in_sizes, int n_in,
                              void* d_out, int out_size)
{
    const float* query = (const float*)d_in[0];
    const float* key   = (const float*)d_in[1];
    const float* value = (const float*)d_in[2];
    const float* wq_w  = (const float*)d_in[3];
    const float* wq_b  = (const float*)d_in[4];
    const float* wk_w  = (const float*)d_in[5];
    const float* wk_b  = (const float*)d_in[6];
    const float* wv_w  = (const float*)d_in[7];
    const float* wv_b  = (const float*)d_in[8];
    const float* fc_w  = (const float*)d_in[9];
    const float* fc_b  = (const float*)d_in[10];
    const int* causal  = (const int*)d_in[11];

    const int L = in_sizes[0] / E_DIM;
    const int S = in_sizes[1] / E_DIM;

    float* out = (float*)d_out;
    float* attn_ptr;
    {
        size_t need = (size_t)L * E_DIM + (size_t)H_HEADS * L * S;
        if ((size_t)out_size >= need) attn_ptr = out + (size_t)L * E_DIM;
        else cudaGetSymbolAddress((void**)&attn_ptr, g_attn_fb);
    }

    __nv_bfloat16 *xqh, *xql, *xkh, *xkl, *xvh, *xvl;
    __nv_bfloat16 *wqh, *wql, *wkh, *wkl, *wvh, *wvl, *fch, *fcl;
    __nv_bfloat16 *qh, *ql, *kh, *kl, *vth, *vtl, *oh, *ol;
    cudaGetSymbolAddress((void**)&xqh, g_xq_h); cudaGetSymbolAddress((void**)&xql, g_xq_l);
    cudaGetSymbolAddress((void**)&xkh, g_xk_h); cudaGetSymbolAddress((void**)&xkl, g_xk_l);
    cudaGetSymbolAddress((void**)&xvh, g_xv_h); cudaGetSymbolAddress((void**)&xvl, g_xv_l);
    cudaGetSymbolAddress((void**)&wqh, g_wq_h); cudaGetSymbolAddress((void**)&wql, g_wq_l);
    cudaGetSymbolAddress((void**)&wkh, g_wk_h); cudaGetSymbolAddress((void**)&wkl, g_wk_l);
    cudaGetSymbolAddress((void**)&wvh, g_wv_h); cudaGetSymbolAddress((void**)&wvl, g_wv_l);
    cudaGetSymbolAddress((void**)&fch, g_fc_h); cudaGetSymbolAddress((void**)&fcl, g_fc_l);
    cudaGetSymbolAddress((void**)&qh, g_q_h);   cudaGetSymbolAddress((void**)&ql, g_q_l);
    cudaGetSymbolAddress((void**)&kh, g_k_h);   cudaGetSymbolAddress((void**)&kl, g_k_l);
    cudaGetSymbolAddress((void**)&vth, g_vt_h); cudaGetSymbolAddress((void**)&vtl, g_vt_l);
    cudaGetSymbolAddress((void**)&oh, g_o_h);   cudaGetSymbolAddress((void**)&ol, g_o_l);

    const int GEMM_SMEM   = 1024 + 2 * 65536;
    const int SCORES_SMEM = 1024 + 32768 + 2 * 32768;
    const int PV_SMEM     = 1024 + 2 * 49152;
    cudaFuncSetAttribute(qkv_hmma,    cudaFuncAttributeMaxDynamicSharedMemorySize, GEMM_SMEM);
    cudaFuncSetAttribute(fc_hmma,     cudaFuncAttributeMaxDynamicSharedMemorySize, GEMM_SMEM);
    cudaFuncSetAttribute(scores_hmma, cudaFuncAttributeMaxDynamicSharedMemorySize, SCORES_SMEM);
    cudaFuncSetAttribute(pv_hmma,     cudaFuncAttributeMaxDynamicSharedMemorySize, PV_SMEM);

    // launch 0: all hi/lo conversions fused
    {
        const int na4 = (L * E_DIM) / 4, nw4 = (E_DIM * E_DIM) / 4;
        cvt_all<<<1024, 256>>>(query, key, value, wq_w, wk_w, wv_w, fc_w,
                               xqh, xql, xkh, xkl, xvh, xvl,
                               wqh, wql, wkh, wkl, wvh, wvl, fch, fcl,
                               na4, nw4);
    }

    // launch 1: Q/K/V projections merged (512 threads)
    {
        dim3 grid(E_DIM / 128, L / 128, 3);
        qkv_hmma<<<grid, 512, GEMM_SMEM>>>(
            xqh, xql, xkh, xkl, xvh, xvl,
            wqh, wql, wkh, wkl, wvh, wvl,
            wq_b, wk_b, wv_b,
            qh, ql, kh, kl, vth, vtl,
            E_DIM, E_DIM, S);
    }

    // launch 2: scores (512 threads)
    {
        dim3 grid(S / (128 * SC_NT), L / 128, H_HEADS);
        scores_hmma<<<grid, 512, SCORES_SMEM>>>(qh, ql, kh, kl, attn_ptr, L, S);
    }

    // launch 3: softmax
    softmax_kernel<<<H_HEADS * L, 256>>>(attn_ptr, L, S, causal);

    // launch 4: PV (pipelined)
    {
        dim3 grid(L / 128, H_HEADS);
        pv_hmma<<<grid, 256, PV_SMEM>>>(attn_ptr, vth, vtl, oh, ol, L, S);
    }

    // launch 5: FC (512 threads)
    {
        dim3 grid(E_DIM / 128, L / 128);
        fc_hmma<<<grid, 512, GEMM_SMEM>>>(oh, ol, fch, fcl, fc_b, out, E_DIM, E_DIM);
    }
}